// round 9
// baseline (speedup 1.0000x reference)
#include <cuda_runtime.h>
#include <cuda_bf16.h>
#include <cstdint>
#include <math.h>

#define NB   8
#define NC   256
#define NH   128
#define NW   128
#define NHW  (NH * NW)        // 16384

// ---------------------------------------------------------------------------
// Scratch (device globals: allocation-guard safe)
// ---------------------------------------------------------------------------
__device__ __nv_bfloat16 g_x_hi[(size_t)NB * NC * NHW];      // [b][c][n]
__device__ __nv_bfloat16 g_x_lo[(size_t)NB * NC * NHW];
__device__ __nv_bfloat16 g_qkv_hi[(size_t)NB * 3 * NC * NHW]; // [b][3C][n]
__device__ __nv_bfloat16 g_qkv_lo[(size_t)NB * 3 * NC * NHW];
__device__ __nv_bfloat16 g_att_hi[(size_t)NB * NC * NHW];
__device__ __nv_bfloat16 g_att_lo[(size_t)NB * NC * NHW];
__device__ __nv_bfloat16 g_w_hi[4 * NC * NC];                // wq,wk,wv,wo [o][c]
__device__ __nv_bfloat16 g_w_lo[4 * NC * NC];
__device__ float g_bias[4 * NC];

// ---------------------------------------------------------------------------
// PTX helpers (sm_80-baseline tensor core path; valid on compute_103)
// ---------------------------------------------------------------------------
__device__ __forceinline__ uint32_t smem_u32(const void* p) {
  uint32_t a;
  asm("{ .reg .u64 t; cvta.to.shared.u64 t, %1; cvt.u32.u64 %0, t; }"
      : "=r"(a) : "l"(p));
  return a;
}
__device__ __forceinline__ void cp_async16(uint32_t sdst, const void* gsrc) {
  asm volatile("cp.async.cg.shared.global [%0], [%1], 16;"
               :: "r"(sdst), "l"(gsrc));
}
#define CP_COMMIT() asm volatile("cp.async.commit_group;" ::: "memory")
#define CP_WAIT0()  asm volatile("cp.async.wait_group 0;" ::: "memory")
#define CP_WAIT1()  asm volatile("cp.async.wait_group 1;" ::: "memory")

__device__ __forceinline__ void ldsm_x4(uint32_t* r, uint32_t addr) {
  asm volatile("ldmatrix.sync.aligned.m8n8.x4.shared.b16 {%0,%1,%2,%3}, [%4];"
               : "=r"(r[0]), "=r"(r[1]), "=r"(r[2]), "=r"(r[3]) : "r"(addr));
}
__device__ __forceinline__ void ldsm_x4_t(uint32_t* r, uint32_t addr) {
  asm volatile("ldmatrix.sync.aligned.m8n8.x4.trans.shared.b16 {%0,%1,%2,%3}, [%4];"
               : "=r"(r[0]), "=r"(r[1]), "=r"(r[2]), "=r"(r[3]) : "r"(addr));
}
__device__ __forceinline__ void mma_bf16(float* d, const uint32_t* a,
                                         uint32_t b0, uint32_t b1) {
  asm volatile(
      "mma.sync.aligned.m16n8k16.row.col.f32.bf16.bf16.f32 "
      "{%0,%1,%2,%3}, {%4,%5,%6,%7}, {%8,%9}, {%0,%1,%2,%3};"
      : "+f"(d[0]), "+f"(d[1]), "+f"(d[2]), "+f"(d[3])
      : "r"(a[0]), "r"(a[1]), "r"(a[2]), "r"(a[3]), "r"(b0), "r"(b1));
}
__device__ __forceinline__ uint32_t pack_hi(float a, float b) {
  __nv_bfloat162 p = {__float2bfloat16(a), __float2bfloat16(b)};
  return *(uint32_t*)&p;
}
__device__ __forceinline__ uint32_t pack_lo(float a, float b) {
  __nv_bfloat16 ha = __float2bfloat16(a), hb = __float2bfloat16(b);
  __nv_bfloat162 p = {__float2bfloat16(a - __bfloat162float(ha)),
                      __float2bfloat16(b - __bfloat162float(hb))};
  return *(uint32_t*)&p;
}

// ---------------------------------------------------------------------------
// Elementwise bf16 split: fp32 -> hi + lo (same layout)
// ---------------------------------------------------------------------------
__global__ __launch_bounds__(256) void split_f32(
    const float* __restrict__ X, __nv_bfloat16* __restrict__ H,
    __nv_bfloat16* __restrict__ L) {
  int i = blockIdx.x * 256 + threadIdx.x;
  float4 v = ((const float4*)X)[i];
  ((uint2*)H)[i] = make_uint2(pack_hi(v.x, v.y), pack_hi(v.z, v.w));
  ((uint2*)L)[i] = make_uint2(pack_lo(v.x, v.y), pack_lo(v.z, v.w));
}

__global__ __launch_bounds__(256) void convert_w(
    const float* __restrict__ w0, const float* __restrict__ w1,
    const float* __restrict__ w2, const float* __restrict__ w3,
    const float* __restrict__ b0, const float* __restrict__ b1,
    const float* __restrict__ b2, const float* __restrict__ b3,
    __nv_bfloat16* __restrict__ H, __nv_bfloat16* __restrict__ L) {
  const float* ws[4] = {w0, w1, w2, w3};
  const float* bs[4] = {b0, b1, b2, b3};
  int m = blockIdx.y;
  int i = blockIdx.x * 256 + threadIdx.x;
  float v = ws[m][i];
  __nv_bfloat16 h = __float2bfloat16(v);
  H[m * NC * NC + i] = h;
  L[m * NC * NC + i] = __float2bfloat16(v - __bfloat162float(h));
  if (blockIdx.x == 0) g_bias[m * NC + threadIdx.x] = bs[m][threadIdx.x];
}

// ---------------------------------------------------------------------------
// mma.sync bf16-split GEMM: D[o][n] = sum_c W[o][c] * X[c][n] + bias[o]
// CTA 128x128, K chunks 32, 3-stage cp.async ring, 8 warps (4 o x 2 n).
// ---------------------------------------------------------------------------
#define OFF_AH   0
#define OFF_AL   10240                 // 128*80
#define OFF_BH   20480
#define OFF_BL   29184                 // + 32*272
#define BUF_BYTES 37888
#define SMEM_GEMM (3 * BUF_BYTES)      // 113664

__global__ __launch_bounds__(256, 2) void gemm_mma(
    const __nv_bfloat16* __restrict__ Xh, const __nv_bfloat16* __restrict__ Xl,
    const __nv_bfloat16* __restrict__ Wh, const __nv_bfloat16* __restrict__ Wl,
    const float* __restrict__ bias, float* __restrict__ Yf,
    __nv_bfloat16* __restrict__ Yh, __nv_bfloat16* __restrict__ Yl,
    int ocnt) {
  extern __shared__ __align__(16) char sm[];
  const uint32_t smb = smem_u32(sm);

  const int tid  = threadIdx.x;
  const int lane = tid & 31;
  const int wid  = tid >> 5;
  const int wm   = wid & 3;
  const int wn   = wid >> 2;
  const int b    = blockIdx.z;
  const int o0   = blockIdx.x * 128;
  const int n0   = blockIdx.y * 128;

  const __nv_bfloat16* Xbh = Xh + (size_t)b * NC * NHW + n0;
  const __nv_bfloat16* Xbl = Xl + (size_t)b * NC * NHW + n0;
  const __nv_bfloat16* Wbh = Wh + (size_t)o0 * NC;
  const __nv_bfloat16* Wbl = Wl + (size_t)o0 * NC;

  const int a_row0 = tid >> 2, a_seg = tid & 3;
  const int b_row0 = tid >> 4, b_seg = tid & 15;

  float acc[2][8][4];
#pragma unroll
  for (int mt = 0; mt < 2; mt++)
#pragma unroll
    for (int nt = 0; nt < 8; nt++)
#pragma unroll
      for (int e = 0; e < 4; e++) acc[mt][nt][e] = 0.f;

  const int lr = lane & 15, lc = lane >> 4;
  uint32_t a_base = (uint32_t)((wm * 32 + lr) * 80 + lc * 16);
  uint32_t b_base = (uint32_t)(lr * 272 + wn * 128 + lc * 16);

  auto stage = [&](int it, int slot) {
    const int c0 = it * 32;
    const uint32_t sb = smb + slot * BUF_BYTES;
#pragma unroll
    for (int r = 0; r < 2; r++) {
      int row = a_row0 + r * 64;
      uint32_t so = (uint32_t)(row * 80 + a_seg * 16);
      cp_async16(sb + OFF_AH + so, Wbh + (size_t)row * NC + c0 + a_seg * 8);
      cp_async16(sb + OFF_AL + so, Wbl + (size_t)row * NC + c0 + a_seg * 8);
    }
#pragma unroll
    for (int r = 0; r < 2; r++) {
      int row = b_row0 + r * 16;
      uint32_t so = (uint32_t)(row * 272 + b_seg * 16);
      cp_async16(sb + OFF_BH + so, Xbh + (size_t)(c0 + row) * NHW + b_seg * 8);
      cp_async16(sb + OFF_BL + so, Xbl + (size_t)(c0 + row) * NHW + b_seg * 8);
    }
    CP_COMMIT();
  };

  stage(0, 0);
  stage(1, 1);

  int slot = 0;
  for (int it = 0; it < 8; it++) {
    if (it < 7) { CP_WAIT1(); } else { CP_WAIT0(); }
    __syncthreads();           // data visible + prior readers of pslot done
    int pslot = slot + 2 >= 3 ? slot - 1 : slot + 2;
    if (it + 2 < 8) stage(it + 2, pslot);

    const uint32_t sb = smb + slot * BUF_BYTES;
#pragma unroll
    for (int ks = 0; ks < 2; ks++) {
      uint32_t ah[2][4], al[2][4];
#pragma unroll
      for (int mt = 0; mt < 2; mt++) {
        uint32_t ao = sb + a_base + (uint32_t)(mt * 16 * 80 + ks * 32);
        ldsm_x4(ah[mt], ao + OFF_AH);
        ldsm_x4(al[mt], ao + OFF_AL);
      }
#pragma unroll
      for (int nt2 = 0; nt2 < 4; nt2++) {
        uint32_t bh[4], bl[4];
        uint32_t bo = sb + b_base + (uint32_t)(ks * 16 * 272 + nt2 * 32);
        ldsm_x4_t(bh, bo + OFF_BH);
        ldsm_x4_t(bl, bo + OFF_BL);
        mma_bf16(acc[0][nt2 * 2],     ah[0], bh[0], bh[1]);   // hi*hi
        mma_bf16(acc[0][nt2 * 2 + 1], ah[0], bh[2], bh[3]);
        mma_bf16(acc[1][nt2 * 2],     ah[1], bh[0], bh[1]);
        mma_bf16(acc[1][nt2 * 2 + 1], ah[1], bh[2], bh[3]);
        mma_bf16(acc[0][nt2 * 2],     ah[0], bl[0], bl[1]);   // hi*lo
        mma_bf16(acc[0][nt2 * 2 + 1], ah[0], bl[2], bl[3]);
        mma_bf16(acc[1][nt2 * 2],     ah[1], bl[0], bl[1]);
        mma_bf16(acc[1][nt2 * 2 + 1], ah[1], bl[2], bl[3]);
        mma_bf16(acc[0][nt2 * 2],     al[0], bh[0], bh[1]);   // lo*hi
        mma_bf16(acc[0][nt2 * 2 + 1], al[0], bh[2], bh[3]);
        mma_bf16(acc[1][nt2 * 2],     al[1], bh[0], bh[1]);
        mma_bf16(acc[1][nt2 * 2 + 1], al[1], bh[2], bh[3]);
      }
    }
    // NOTE: no trailing __syncthreads — the leading barrier of the next
    // iteration (after CP_WAIT) orders these reads before any slot reuse.
    slot = slot + 1 >= 3 ? 0 : slot + 1;
  }
  __syncthreads();

#pragma unroll
  for (int mt = 0; mt < 2; mt++) {
    int o = o0 + wm * 32 + mt * 16 + (lane >> 2);
    float bv0 = __ldg(bias + o);
    float bv1 = __ldg(bias + o + 8);
#pragma unroll
    for (int nt = 0; nt < 8; nt++) {
      int n = n0 + wn * 64 + nt * 8 + (lane & 3) * 2;
      float v00 = acc[mt][nt][0] + bv0, v01 = acc[mt][nt][1] + bv0;
      float v10 = acc[mt][nt][2] + bv1, v11 = acc[mt][nt][3] + bv1;
      size_t off0 = ((size_t)b * ocnt + o) * NHW + n;
      size_t off1 = ((size_t)b * ocnt + o + 8) * NHW + n;
      if (Yf) {
        *(float2*)(Yf + off0) = make_float2(v00, v01);
        *(float2*)(Yf + off1) = make_float2(v10, v11);
      } else {
        *(uint32_t*)(Yh + off0) = pack_hi(v00, v01);
        *(uint32_t*)(Yh + off1) = pack_hi(v10, v11);
        *(uint32_t*)(Yl + off0) = pack_lo(v00, v01);
        *(uint32_t*)(Yl + off1) = pack_lo(v10, v11);
      }
    }
  }
}

// ---------------------------------------------------------------------------
// Persistent tensor-core attention: grid = #SMs, each CTA walks channels
// with stride gridDim.x. smem = 3-slot K/V ring (3 x 69632 B). Q is consumed
// directly from gmem into MMA A-fragments (no smem, no cross-warp reuse).
// While S(c) computes, K(c+1) prefetches; while P*V(c) computes, V(c+1)
// prefetches. One cp.async commit per phase keeps wait_group 1 exact.
// ---------------------------------------------------------------------------
#define KV_SLOT   69632                 // hi (34816) + lo (34816)
#define SMEM_ATTN (3 * KV_SLOT)         // 208896

__global__ __launch_bounds__(256) void attn_mma(
    const __nv_bfloat16* __restrict__ QKVh,
    const __nv_bfloat16* __restrict__ QKVl,
    __nv_bfloat16* __restrict__ Oh, __nv_bfloat16* __restrict__ Ol) {
  extern __shared__ __align__(16) char sm[];
  const uint32_t smb = smem_u32(sm);

  const int tid  = threadIdx.x;
  const int lane = tid & 31;
  const int wid  = tid >> 5;
  const int lr = lane & 15, lc = lane >> 4;
  const int g = lane >> 2, tig = lane & 3;
  const int r0 = wid * 16;
  const int srow = tid >> 4, sseg = tid & 15;
  const int nchan = NB * NC;

  auto stage_kv = [&](int slot, size_t goff) {
    const uint32_t so0 = smb + (uint32_t)(slot * KV_SLOT);
#pragma unroll
    for (int r = 0; r < 8; r++) {
      int row = srow + r * 16;
      uint32_t so = (uint32_t)(row * 272 + sseg * 16);
      cp_async16(so0 + so,         QKVh + goff + row * 128 + sseg * 8);
      cp_async16(so0 + 34816 + so, QKVl + goff + row * 128 + sseg * 8);
    }
    CP_COMMIT();
  };

  // channel q -> base offsets in [b][3C][n]: b = q>>8, c = q&255
  auto qoff = [&](int q) {
    return ((size_t)(q >> 8) * 3 * NC + (q & 255)) * NHW;
  };

  // Prologue: K(c0) -> slot0 [group], V(c0) -> slot1 [group]
  const int c0 = blockIdx.x;
  if (c0 < nchan) {
    stage_kv(0, qoff(c0) + (size_t)NC * NHW);
    stage_kv(1, qoff(c0) + (size_t)2 * NC * NHW);
  }

  int kslot = 0;
  for (int q = c0; q < nchan; q += gridDim.x) {
    const size_t qb = qoff(q);
    int vslot = kslot + 1; if (vslot >= 3) vslot -= 3;
    int pkslot = kslot + 2; if (pkslot >= 3) pkslot -= 3;
    const int qn = q + gridDim.x;

    CP_WAIT1();          // K(q) arrived (V(q) may pend)
    __syncthreads();     // all threads' copies visible; prior readers done

    // Q fragments straight from gmem (A-frag layout of m16n8k16)
    uint32_t qfh[8][4], qfl[8][4];
    {
      const __nv_bfloat16* q0h = QKVh + qb + (size_t)(r0 + g) * 128;
      const __nv_bfloat16* q1h = q0h + 8 * 128;
      const __nv_bfloat16* q0l = QKVl + qb + (size_t)(r0 + g) * 128;
      const __nv_bfloat16* q1l = q0l + 8 * 128;
#pragma unroll
      for (int ks = 0; ks < 8; ks++) {
        int e0 = ks * 16 + 2 * tig, e1 = e0 + 8;
        qfh[ks][0] = *(const uint32_t*)(q0h + e0);
        qfh[ks][1] = *(const uint32_t*)(q1h + e0);
        qfh[ks][2] = *(const uint32_t*)(q0h + e1);
        qfh[ks][3] = *(const uint32_t*)(q1h + e1);
        qfl[ks][0] = *(const uint32_t*)(q0l + e0);
        qfl[ks][1] = *(const uint32_t*)(q1l + e0);
        qfl[ks][2] = *(const uint32_t*)(q0l + e1);
        qfl[ks][3] = *(const uint32_t*)(q1l + e1);
      }
    }

    // Prefetch K(next) into pkslot (overlaps S + PV)
    if (qn < nchan) stage_kv(pkslot, qoff(qn) + (size_t)NC * NHW);
    else CP_COMMIT();    // empty group keeps wait_group counting exact

    // S = Q K^T from kslot
    float acc[16][4];
#pragma unroll
    for (int j = 0; j < 16; j++)
#pragma unroll
      for (int e = 0; e < 4; e++) acc[j][e] = 0.f;

    const uint32_t kbase = smb + (uint32_t)(kslot * KV_SLOT);
#pragma unroll
    for (int ks = 0; ks < 8; ks++) {
#pragma unroll
      for (int nt = 0; nt < 8; nt += 2) {
        uint32_t kh0[4], kl0[4], kh1[4], kl1[4];
        uint32_t bo0 = kbase + (uint32_t)((nt * 16 + lr) * 272 + ks * 32 + lc * 16);
        uint32_t bo1 = bo0 + 16 * 272;
        ldsm_x4(kh0, bo0);
        ldsm_x4(kl0, bo0 + 34816);
        ldsm_x4(kh1, bo1);
        ldsm_x4(kl1, bo1 + 34816);
        mma_bf16(acc[2 * nt],     qfh[ks], kh0[0], kh0[2]);
        mma_bf16(acc[2 * nt + 1], qfh[ks], kh0[1], kh0[3]);
        mma_bf16(acc[2 * nt + 2], qfh[ks], kh1[0], kh1[2]);
        mma_bf16(acc[2 * nt + 3], qfh[ks], kh1[1], kh1[3]);
        mma_bf16(acc[2 * nt],     qfh[ks], kl0[0], kl0[2]);
        mma_bf16(acc[2 * nt + 1], qfh[ks], kl0[1], kl0[3]);
        mma_bf16(acc[2 * nt + 2], qfh[ks], kl1[0], kl1[2]);
        mma_bf16(acc[2 * nt + 3], qfh[ks], kl1[1], kl1[3]);
        mma_bf16(acc[2 * nt],     qfl[ks], kh0[0], kh0[2]);
        mma_bf16(acc[2 * nt + 1], qfl[ks], kh0[1], kh0[3]);
        mma_bf16(acc[2 * nt + 2], qfl[ks], kh1[0], kh1[2]);
        mma_bf16(acc[2 * nt + 3], qfl[ks], kh1[1], kh1[3]);
      }
    }

    // Register softmax (rows g and g+8; 4 lanes share a row)
    const float SCALE = 0.42044820762685725f;   // 32^(-1/4)
    float mA = -1e30f, mB = -1e30f;
#pragma unroll
    for (int j = 0; j < 16; j++) {
      acc[j][0] *= SCALE; acc[j][1] *= SCALE;
      acc[j][2] *= SCALE; acc[j][3] *= SCALE;
      mA = fmaxf(mA, fmaxf(acc[j][0], acc[j][1]));
      mB = fmaxf(mB, fmaxf(acc[j][2], acc[j][3]));
    }
    mA = fmaxf(mA, __shfl_xor_sync(0xffffffffu, mA, 1));
    mA = fmaxf(mA, __shfl_xor_sync(0xffffffffu, mA, 2));
    mB = fmaxf(mB, __shfl_xor_sync(0xffffffffu, mB, 1));
    mB = fmaxf(mB, __shfl_xor_sync(0xffffffffu, mB, 2));
    float sA = 0.f, sB = 0.f;
#pragma unroll
    for (int j = 0; j < 16; j++) {
      acc[j][0] = __expf(acc[j][0] - mA);
      acc[j][1] = __expf(acc[j][1] - mA);
      acc[j][2] = __expf(acc[j][2] - mB);
      acc[j][3] = __expf(acc[j][3] - mB);
      sA += acc[j][0] + acc[j][1];
      sB += acc[j][2] + acc[j][3];
    }
    sA += __shfl_xor_sync(0xffffffffu, sA, 1);
    sA += __shfl_xor_sync(0xffffffffu, sA, 2);
    sB += __shfl_xor_sync(0xffffffffu, sB, 1);
    sB += __shfl_xor_sync(0xffffffffu, sB, 2);
    const float rA = 1.0f / sA, rB = 1.0f / sB;

    // P accumulator fragments -> A-operand fragments (hi/lo), in registers
    uint32_t ph[8][4], pl[8][4];
#pragma unroll
    for (int ky = 0; ky < 8; ky++) {
      const int j0 = 2 * ky, j1 = 2 * ky + 1;
      float p00 = acc[j0][0] * rA, p01 = acc[j0][1] * rA;
      float p02 = acc[j0][2] * rB, p03 = acc[j0][3] * rB;
      float p10 = acc[j1][0] * rA, p11 = acc[j1][1] * rA;
      float p12 = acc[j1][2] * rB, p13 = acc[j1][3] * rB;
      ph[ky][0] = pack_hi(p00, p01); ph[ky][1] = pack_hi(p02, p03);
      ph[ky][2] = pack_hi(p10, p11); ph[ky][3] = pack_hi(p12, p13);
      pl[ky][0] = pack_lo(p00, p01); pl[ky][1] = pack_lo(p02, p03);
      pl[ky][2] = pack_lo(p10, p11); pl[ky][3] = pack_lo(p12, p13);
    }

    CP_WAIT1();          // V(q) arrived (K(next) may pend)
    __syncthreads();     // all K(q) reads done before V(next) overwrites kslot

    // Prefetch V(next) into kslot (K(q)'s old slot — now safe)
    if (qn < nchan) stage_kv(kslot, qoff(qn) + (size_t)2 * NC * NHW);
    else CP_COMMIT();

    // O = P V from vslot
    float oac[16][4];
#pragma unroll
    for (int j = 0; j < 16; j++)
#pragma unroll
      for (int e = 0; e < 4; e++) oac[j][e] = 0.f;

    const uint32_t vbase = smb + (uint32_t)(vslot * KV_SLOT);
#pragma unroll
    for (int ky = 0; ky < 8; ky++) {
#pragma unroll
      for (int nt = 0; nt < 8; nt += 2) {
        uint32_t vh0[4], vl0[4], vh1[4], vl1[4];
        uint32_t bo0 = vbase + (uint32_t)((ky * 16 + lr) * 272 + nt * 32 + lc * 16);
        uint32_t bo1 = bo0 + 32;
        ldsm_x4_t(vh0, bo0);
        ldsm_x4_t(vl0, bo0 + 34816);
        ldsm_x4_t(vh1, bo1);
        ldsm_x4_t(vl1, bo1 + 34816);
        mma_bf16(oac[2 * nt],     ph[ky], vh0[0], vh0[1]);
        mma_bf16(oac[2 * nt + 1], ph[ky], vh0[2], vh0[3]);
        mma_bf16(oac[2 * nt + 2], ph[ky], vh1[0], vh1[1]);
        mma_bf16(oac[2 * nt + 3], ph[ky], vh1[2], vh1[3]);
        mma_bf16(oac[2 * nt],     ph[ky], vl0[0], vl0[1]);
        mma_bf16(oac[2 * nt + 1], ph[ky], vl0[2], vl0[3]);
        mma_bf16(oac[2 * nt + 2], ph[ky], vl1[0], vl1[1]);
        mma_bf16(oac[2 * nt + 3], ph[ky], vl1[2], vl1[3]);
        mma_bf16(oac[2 * nt],     pl[ky], vh0[0], vh0[1]);
        mma_bf16(oac[2 * nt + 1], pl[ky], vh0[2], vh0[3]);
        mma_bf16(oac[2 * nt + 2], pl[ky], vh1[0], vh1[1]);
        mma_bf16(oac[2 * nt + 3], pl[ky], vh1[2], vh1[3]);
      }
    }

    // Epilogue: write O hi/lo bf16 at [q][row*128+col]
    const size_t ob = (size_t)q * NHW;
    const int row0 = r0 + g, row1 = r0 + g + 8;
#pragma unroll
    for (int j = 0; j < 16; j++) {
      int col = j * 8 + tig * 2;
      size_t o0 = ob + (size_t)row0 * 128 + col;
      size_t o1 = ob + (size_t)row1 * 128 + col;
      *(uint32_t*)(Oh + o0) = pack_hi(oac[j][0], oac[j][1]);
      *(uint32_t*)(Oh + o1) = pack_hi(oac[j][2], oac[j][3]);
      *(uint32_t*)(Ol + o0) = pack_lo(oac[j][0], oac[j][1]);
      *(uint32_t*)(Ol + o1) = pack_lo(oac[j][2], oac[j][3]);
    }

    kslot = pkslot;      // ring advance: slot(K) += 2 (mod 3)
  }
}

// ---------------------------------------------------------------------------
extern "C" void kernel_launch(void* const* d_in, const int* in_sizes, int n_in,
                              void* d_out, int out_size) {
  const float* x  = (const float*)d_in[0];
  const float* wq = (const float*)d_in[1];
  const float* bq = (const float*)d_in[2];
  const float* wk = (const float*)d_in[3];
  const float* bk = (const float*)d_in[4];
  const float* wv = (const float*)d_in[5];
  const float* bv = (const float*)d_in[6];
  const float* wo = (const float*)d_in[7];
  const float* bo = (const float*)d_in[8];

  __nv_bfloat16 *xh, *xl, *qkvh, *qkvl, *ath, *atl, *wh, *wl;
  float* bias;
  cudaGetSymbolAddress((void**)&xh,   g_x_hi);
  cudaGetSymbolAddress((void**)&xl,   g_x_lo);
  cudaGetSymbolAddress((void**)&qkvh, g_qkv_hi);
  cudaGetSymbolAddress((void**)&qkvl, g_qkv_lo);
  cudaGetSymbolAddress((void**)&ath,  g_att_hi);
  cudaGetSymbolAddress((void**)&atl,  g_att_lo);
  cudaGetSymbolAddress((void**)&wh,   g_w_hi);
  cudaGetSymbolAddress((void**)&wl,   g_w_lo);
  cudaGetSymbolAddress((void**)&bias, g_bias);

  int nsm = 148;
  cudaDeviceGetAttribute(&nsm, cudaDevAttrMultiProcessorCount, 0);

  cudaFuncSetAttribute(gemm_mma,
                       cudaFuncAttributeMaxDynamicSharedMemorySize, SMEM_GEMM);
  cudaFuncSetAttribute(attn_mma,
                       cudaFuncAttributeMaxDynamicSharedMemorySize, SMEM_ATTN);

  // Convert inputs
  split_f32<<<NB * NC * NHW / 4 / 256, 256>>>(x, xh, xl);
  convert_w<<<dim3(NC * NC / 256, 4), 256>>>(wq, wk, wv, wo, bq, bk, bv, bo, wh, wl);

  // Fused QKV projection -> bf16 hi/lo
  gemm_mma<<<dim3(6, NHW / 128, NB), 256, SMEM_GEMM>>>(
      xh, xl, wh, wl, bias, nullptr, qkvh, qkvl, 3 * NC);

  // Persistent tensor-core attention -> bf16 hi/lo
  attn_mma<<<nsm, 256, SMEM_ATTN>>>(qkvh, qkvl, ath, atl);

  // Output projection -> fp32 d_out
  gemm_mma<<<dim3(2, NHW / 128, NB), 256, SMEM_GEMM>>>(
      ath, atl, wh + 3 * NC * NC, wl + 3 * NC * NC, bias + 3 * NC,
      (float*)d_out, nullptr, nullptr, NC);
}

// round 10
// speedup vs baseline: 1.0231x; 1.0231x over previous
#include <cuda_runtime.h>
#include <cuda_bf16.h>
#include <cstdint>
#include <math.h>

#define NB   8
#define NC   256
#define NH   128
#define NW   128
#define NHW  (NH * NW)        // 16384

// ---------------------------------------------------------------------------
// Scratch (device globals: allocation-guard safe)
// ---------------------------------------------------------------------------
__device__ __nv_bfloat16 g_x_hi[(size_t)NB * NC * NHW];      // [b][c][n]
__device__ __nv_bfloat16 g_x_lo[(size_t)NB * NC * NHW];
__device__ __nv_bfloat16 g_qkv_hi[(size_t)NB * 3 * NC * NHW]; // [b][3C][n]
__device__ __nv_bfloat16 g_qkv_lo[(size_t)NB * 3 * NC * NHW];
__device__ __nv_bfloat16 g_att_hi[(size_t)NB * NC * NHW];
__device__ __nv_bfloat16 g_att_lo[(size_t)NB * NC * NHW];
__device__ __nv_bfloat16 g_w_hi[4 * NC * NC];                // wq,wk,wv,wo [o][c]
__device__ __nv_bfloat16 g_w_lo[4 * NC * NC];
__device__ float g_bias[4 * NC];

// ---------------------------------------------------------------------------
// PTX helpers (sm_80-baseline tensor core path; valid on compute_103)
// ---------------------------------------------------------------------------
__device__ __forceinline__ uint32_t smem_u32(const void* p) {
  uint32_t a;
  asm("{ .reg .u64 t; cvta.to.shared.u64 t, %1; cvt.u32.u64 %0, t; }"
      : "=r"(a) : "l"(p));
  return a;
}
__device__ __forceinline__ void cp_async16(uint32_t sdst, const void* gsrc) {
  asm volatile("cp.async.cg.shared.global [%0], [%1], 16;"
               :: "r"(sdst), "l"(gsrc));
}
#define CP_COMMIT() asm volatile("cp.async.commit_group;" ::: "memory")
#define CP_WAIT0()  asm volatile("cp.async.wait_group 0;" ::: "memory")
#define CP_WAIT1()  asm volatile("cp.async.wait_group 1;" ::: "memory")

__device__ __forceinline__ void ldsm_x4(uint32_t* r, uint32_t addr) {
  asm volatile("ldmatrix.sync.aligned.m8n8.x4.shared.b16 {%0,%1,%2,%3}, [%4];"
               : "=r"(r[0]), "=r"(r[1]), "=r"(r[2]), "=r"(r[3]) : "r"(addr));
}
__device__ __forceinline__ void ldsm_x4_t(uint32_t* r, uint32_t addr) {
  asm volatile("ldmatrix.sync.aligned.m8n8.x4.trans.shared.b16 {%0,%1,%2,%3}, [%4];"
               : "=r"(r[0]), "=r"(r[1]), "=r"(r[2]), "=r"(r[3]) : "r"(addr));
}
__device__ __forceinline__ void mma_bf16(float* d, const uint32_t* a,
                                         uint32_t b0, uint32_t b1) {
  asm volatile(
      "mma.sync.aligned.m16n8k16.row.col.f32.bf16.bf16.f32 "
      "{%0,%1,%2,%3}, {%4,%5,%6,%7}, {%8,%9}, {%0,%1,%2,%3};"
      : "+f"(d[0]), "+f"(d[1]), "+f"(d[2]), "+f"(d[3])
      : "r"(a[0]), "r"(a[1]), "r"(a[2]), "r"(a[3]), "r"(b0), "r"(b1));
}
__device__ __forceinline__ uint32_t pack_hi(float a, float b) {
  __nv_bfloat162 p = {__float2bfloat16(a), __float2bfloat16(b)};
  return *(uint32_t*)&p;
}
__device__ __forceinline__ uint32_t pack_lo(float a, float b) {
  __nv_bfloat16 ha = __float2bfloat16(a), hb = __float2bfloat16(b);
  __nv_bfloat162 p = {__float2bfloat16(a - __bfloat162float(ha)),
                      __float2bfloat16(b - __bfloat162float(hb))};
  return *(uint32_t*)&p;
}

// ---------------------------------------------------------------------------
// Elementwise bf16 split: fp32 -> hi + lo (same layout)
// ---------------------------------------------------------------------------
__global__ __launch_bounds__(256) void split_f32(
    const float* __restrict__ X, __nv_bfloat16* __restrict__ H,
    __nv_bfloat16* __restrict__ L) {
  int i = blockIdx.x * 256 + threadIdx.x;
  float4 v = ((const float4*)X)[i];
  ((uint2*)H)[i] = make_uint2(pack_hi(v.x, v.y), pack_hi(v.z, v.w));
  ((uint2*)L)[i] = make_uint2(pack_lo(v.x, v.y), pack_lo(v.z, v.w));
}

__global__ __launch_bounds__(256) void convert_w(
    const float* __restrict__ w0, const float* __restrict__ w1,
    const float* __restrict__ w2, const float* __restrict__ w3,
    const float* __restrict__ b0, const float* __restrict__ b1,
    const float* __restrict__ b2, const float* __restrict__ b3,
    __nv_bfloat16* __restrict__ H, __nv_bfloat16* __restrict__ L) {
  const float* ws[4] = {w0, w1, w2, w3};
  const float* bs[4] = {b0, b1, b2, b3};
  int m = blockIdx.y;
  int i = blockIdx.x * 256 + threadIdx.x;
  float v = ws[m][i];
  __nv_bfloat16 h = __float2bfloat16(v);
  H[m * NC * NC + i] = h;
  L[m * NC * NC + i] = __float2bfloat16(v - __bfloat162float(h));
  if (blockIdx.x == 0) g_bias[m * NC + threadIdx.x] = bs[m][threadIdx.x];
}

// ---------------------------------------------------------------------------
// mma.sync bf16-split GEMM (R9 version — best measured gemm)
// ---------------------------------------------------------------------------
#define OFF_AH   0
#define OFF_AL   10240                 // 128*80
#define OFF_BH   20480
#define OFF_BL   29184                 // + 32*272
#define BUF_BYTES 37888
#define SMEM_GEMM (3 * BUF_BYTES)      // 113664

__global__ __launch_bounds__(256, 2) void gemm_mma(
    const __nv_bfloat16* __restrict__ Xh, const __nv_bfloat16* __restrict__ Xl,
    const __nv_bfloat16* __restrict__ Wh, const __nv_bfloat16* __restrict__ Wl,
    const float* __restrict__ bias, float* __restrict__ Yf,
    __nv_bfloat16* __restrict__ Yh, __nv_bfloat16* __restrict__ Yl,
    int ocnt) {
  extern __shared__ __align__(16) char sm[];
  const uint32_t smb = smem_u32(sm);

  const int tid  = threadIdx.x;
  const int lane = tid & 31;
  const int wid  = tid >> 5;
  const int wm   = wid & 3;
  const int wn   = wid >> 2;
  const int b    = blockIdx.z;
  const int o0   = blockIdx.x * 128;
  const int n0   = blockIdx.y * 128;

  const __nv_bfloat16* Xbh = Xh + (size_t)b * NC * NHW + n0;
  const __nv_bfloat16* Xbl = Xl + (size_t)b * NC * NHW + n0;
  const __nv_bfloat16* Wbh = Wh + (size_t)o0 * NC;
  const __nv_bfloat16* Wbl = Wl + (size_t)o0 * NC;

  const int a_row0 = tid >> 2, a_seg = tid & 3;
  const int b_row0 = tid >> 4, b_seg = tid & 15;

  float acc[2][8][4];
#pragma unroll
  for (int mt = 0; mt < 2; mt++)
#pragma unroll
    for (int nt = 0; nt < 8; nt++)
#pragma unroll
      for (int e = 0; e < 4; e++) acc[mt][nt][e] = 0.f;

  const int lr = lane & 15, lc = lane >> 4;
  uint32_t a_base = (uint32_t)((wm * 32 + lr) * 80 + lc * 16);
  uint32_t b_base = (uint32_t)(lr * 272 + wn * 128 + lc * 16);

  auto stage = [&](int it, int slot) {
    const int c0 = it * 32;
    const uint32_t sb = smb + slot * BUF_BYTES;
#pragma unroll
    for (int r = 0; r < 2; r++) {
      int row = a_row0 + r * 64;
      uint32_t so = (uint32_t)(row * 80 + a_seg * 16);
      cp_async16(sb + OFF_AH + so, Wbh + (size_t)row * NC + c0 + a_seg * 8);
      cp_async16(sb + OFF_AL + so, Wbl + (size_t)row * NC + c0 + a_seg * 8);
    }
#pragma unroll
    for (int r = 0; r < 2; r++) {
      int row = b_row0 + r * 16;
      uint32_t so = (uint32_t)(row * 272 + b_seg * 16);
      cp_async16(sb + OFF_BH + so, Xbh + (size_t)(c0 + row) * NHW + b_seg * 8);
      cp_async16(sb + OFF_BL + so, Xbl + (size_t)(c0 + row) * NHW + b_seg * 8);
    }
    CP_COMMIT();
  };

  stage(0, 0);
  stage(1, 1);

  int slot = 0;
  for (int it = 0; it < 8; it++) {
    if (it < 7) { CP_WAIT1(); } else { CP_WAIT0(); }
    __syncthreads();
    int pslot = slot + 2 >= 3 ? slot - 1 : slot + 2;
    if (it + 2 < 8) stage(it + 2, pslot);

    const uint32_t sb = smb + slot * BUF_BYTES;
#pragma unroll
    for (int ks = 0; ks < 2; ks++) {
      uint32_t ah[2][4], al[2][4];
#pragma unroll
      for (int mt = 0; mt < 2; mt++) {
        uint32_t ao = sb + a_base + (uint32_t)(mt * 16 * 80 + ks * 32);
        ldsm_x4(ah[mt], ao + OFF_AH);
        ldsm_x4(al[mt], ao + OFF_AL);
      }
#pragma unroll
      for (int nt2 = 0; nt2 < 4; nt2++) {
        uint32_t bh[4], bl[4];
        uint32_t bo = sb + b_base + (uint32_t)(ks * 16 * 272 + nt2 * 32);
        ldsm_x4_t(bh, bo + OFF_BH);
        ldsm_x4_t(bl, bo + OFF_BL);
        mma_bf16(acc[0][nt2 * 2],     ah[0], bh[0], bh[1]);   // hi*hi
        mma_bf16(acc[0][nt2 * 2 + 1], ah[0], bh[2], bh[3]);
        mma_bf16(acc[1][nt2 * 2],     ah[1], bh[0], bh[1]);
        mma_bf16(acc[1][nt2 * 2 + 1], ah[1], bh[2], bh[3]);
        mma_bf16(acc[0][nt2 * 2],     ah[0], bl[0], bl[1]);   // hi*lo
        mma_bf16(acc[0][nt2 * 2 + 1], ah[0], bl[2], bl[3]);
        mma_bf16(acc[1][nt2 * 2],     ah[1], bl[0], bl[1]);
        mma_bf16(acc[1][nt2 * 2 + 1], ah[1], bl[2], bl[3]);
        mma_bf16(acc[0][nt2 * 2],     al[0], bh[0], bh[1]);   // lo*hi
        mma_bf16(acc[0][nt2 * 2 + 1], al[0], bh[2], bh[3]);
        mma_bf16(acc[1][nt2 * 2],     al[1], bh[0], bh[1]);
        mma_bf16(acc[1][nt2 * 2 + 1], al[1], bh[2], bh[3]);
      }
    }
    slot = slot + 1 >= 3 ? 0 : slot + 1;
  }
  __syncthreads();

#pragma unroll
  for (int mt = 0; mt < 2; mt++) {
    int o = o0 + wm * 32 + mt * 16 + (lane >> 2);
    float bv0 = __ldg(bias + o);
    float bv1 = __ldg(bias + o + 8);
#pragma unroll
    for (int nt = 0; nt < 8; nt++) {
      int n = n0 + wn * 64 + nt * 8 + (lane & 3) * 2;
      float v00 = acc[mt][nt][0] + bv0, v01 = acc[mt][nt][1] + bv0;
      float v10 = acc[mt][nt][2] + bv1, v11 = acc[mt][nt][3] + bv1;
      size_t off0 = ((size_t)b * ocnt + o) * NHW + n;
      size_t off1 = ((size_t)b * ocnt + o + 8) * NHW + n;
      if (Yf) {
        *(float2*)(Yf + off0) = make_float2(v00, v01);
        *(float2*)(Yf + off1) = make_float2(v10, v11);
      } else {
        *(uint32_t*)(Yh + off0) = pack_hi(v00, v01);
        *(uint32_t*)(Yh + off1) = pack_hi(v10, v11);
        *(uint32_t*)(Yl + off0) = pack_lo(v00, v01);
        *(uint32_t*)(Yl + off1) = pack_lo(v10, v11);
      }
    }
  }
}

// ---------------------------------------------------------------------------
// Persistent tensor-core attention, R7 compute core.
// smem regions: Q (69632) | K (69632) | V (69632), each hi at +0, lo at +34816.
// Per channel q:  wait QK(q) -> S -> sync -> prefetch QK(q+1) -> softmax/pack
//                 -> wait V(q) -> PV -> sync -> prefetch V(q+1) -> store O(q).
// One cp.async group per phase (empty commits at tail) => wait_group 1 exact:
//   top-of-loop wait leaves V(q) pending; pre-PV wait leaves QK(q+1) pending.
// ---------------------------------------------------------------------------
#define AT_Q 0
#define AT_K 69632
#define AT_V 139264
#define SMEM_ATTN 208896

__global__ __launch_bounds__(256) void attn_mma(
    const __nv_bfloat16* __restrict__ QKVh,
    const __nv_bfloat16* __restrict__ QKVl,
    __nv_bfloat16* __restrict__ Oh, __nv_bfloat16* __restrict__ Ol) {
  extern __shared__ __align__(16) char sm[];
  const uint32_t smb = smem_u32(sm);

  const int tid  = threadIdx.x;
  const int lane = tid & 31;
  const int wid  = tid >> 5;
  const int lr = lane & 15, lc = lane >> 4;
  const int g = lane >> 2, tig = lane & 3;
  const int r0 = wid * 16;
  const int srow = tid >> 4, sseg = tid & 15;
  const int nchan = NB * NC;

  auto stage128 = [&](uint32_t region, size_t goff) {
    const uint32_t sb = smb + region;
#pragma unroll
    for (int r = 0; r < 8; r++) {
      int row = srow + r * 16;
      uint32_t so = (uint32_t)(row * 272 + sseg * 16);
      cp_async16(sb + so,         QKVh + goff + row * 128 + sseg * 8);
      cp_async16(sb + 34816 + so, QKVl + goff + row * 128 + sseg * 8);
    }
  };
  auto qoff = [&](int q) {
    return ((size_t)(q >> 8) * 3 * NC + (q & 255)) * NHW;
  };

  // Prologue: QK(c0) [group], V(c0) [group]
  const int c0 = blockIdx.x;
  stage128(AT_Q, qoff(c0));
  stage128(AT_K, qoff(c0) + (size_t)NC * NHW);
  CP_COMMIT();
  stage128(AT_V, qoff(c0) + (size_t)2 * NC * NHW);
  CP_COMMIT();

  for (int q = c0; q < nchan; q += gridDim.x) {
    const int qn = q + gridDim.x;

    CP_WAIT1();          // QK(q) done (V(q) may pend)
    __syncthreads();     // visible to all warps; prior epilogue done

    // S = Q K^T
    float acc[16][4];
#pragma unroll
    for (int j = 0; j < 16; j++)
#pragma unroll
      for (int e = 0; e < 4; e++) acc[j][e] = 0.f;

#pragma unroll
    for (int ks = 0; ks < 8; ks++) {
      uint32_t qh[4], ql[4];
      uint32_t ao = smb + AT_Q + (uint32_t)((r0 + lr) * 272 + ks * 32 + lc * 16);
      ldsm_x4(qh, ao);
      ldsm_x4(ql, ao + 34816);
#pragma unroll
      for (int nt = 0; nt < 8; nt += 2) {
        uint32_t kh0[4], kl0[4], kh1[4], kl1[4];
        uint32_t bo0 = smb + AT_K + (uint32_t)((nt * 16 + lr) * 272 + ks * 32 + lc * 16);
        uint32_t bo1 = bo0 + 16 * 272;
        ldsm_x4(kh0, bo0);
        ldsm_x4(kl0, bo0 + 34816);
        ldsm_x4(kh1, bo1);
        ldsm_x4(kl1, bo1 + 34816);
        mma_bf16(acc[2 * nt],     qh, kh0[0], kh0[2]);
        mma_bf16(acc[2 * nt + 1], qh, kh0[1], kh0[3]);
        mma_bf16(acc[2 * nt + 2], qh, kh1[0], kh1[2]);
        mma_bf16(acc[2 * nt + 3], qh, kh1[1], kh1[3]);
        mma_bf16(acc[2 * nt],     qh, kl0[0], kl0[2]);
        mma_bf16(acc[2 * nt + 1], qh, kl0[1], kl0[3]);
        mma_bf16(acc[2 * nt + 2], qh, kl1[0], kl1[2]);
        mma_bf16(acc[2 * nt + 3], qh, kl1[1], kl1[3]);
        mma_bf16(acc[2 * nt],     ql, kh0[0], kh0[2]);
        mma_bf16(acc[2 * nt + 1], ql, kh0[1], kh0[3]);
        mma_bf16(acc[2 * nt + 2], ql, kh1[0], kh1[2]);
        mma_bf16(acc[2 * nt + 3], ql, kh1[1], kh1[3]);
      }
    }

    __syncthreads();     // all warps done reading Q,K
    if (qn < nchan) {    // prefetch QK(next) — overlaps softmax + PV + store
      stage128(AT_Q, qoff(qn));
      stage128(AT_K, qoff(qn) + (size_t)NC * NHW);
    }
    CP_COMMIT();         // always: keeps group ledger exact

    // Register softmax (rows g and g+8; 4 lanes share a row)
    const float SCALE = 0.42044820762685725f;   // 32^(-1/4)
    float mA = -1e30f, mB = -1e30f;
#pragma unroll
    for (int j = 0; j < 16; j++) {
      acc[j][0] *= SCALE; acc[j][1] *= SCALE;
      acc[j][2] *= SCALE; acc[j][3] *= SCALE;
      mA = fmaxf(mA, fmaxf(acc[j][0], acc[j][1]));
      mB = fmaxf(mB, fmaxf(acc[j][2], acc[j][3]));
    }
    mA = fmaxf(mA, __shfl_xor_sync(0xffffffffu, mA, 1));
    mA = fmaxf(mA, __shfl_xor_sync(0xffffffffu, mA, 2));
    mB = fmaxf(mB, __shfl_xor_sync(0xffffffffu, mB, 1));
    mB = fmaxf(mB, __shfl_xor_sync(0xffffffffu, mB, 2));
    float sA = 0.f, sB = 0.f;
#pragma unroll
    for (int j = 0; j < 16; j++) {
      acc[j][0] = __expf(acc[j][0] - mA);
      acc[j][1] = __expf(acc[j][1] - mA);
      acc[j][2] = __expf(acc[j][2] - mB);
      acc[j][3] = __expf(acc[j][3] - mB);
      sA += acc[j][0] + acc[j][1];
      sB += acc[j][2] + acc[j][3];
    }
    sA += __shfl_xor_sync(0xffffffffu, sA, 1);
    sA += __shfl_xor_sync(0xffffffffu, sA, 2);
    sB += __shfl_xor_sync(0xffffffffu, sB, 1);
    sB += __shfl_xor_sync(0xffffffffu, sB, 2);
    const float rA = 1.0f / sA, rB = 1.0f / sB;

    // P accumulator fragments -> A-operand fragments (hi/lo), in registers
    uint32_t ph[8][4], pl[8][4];
#pragma unroll
    for (int ky = 0; ky < 8; ky++) {
      const int j0 = 2 * ky, j1 = 2 * ky + 1;
      float p00 = acc[j0][0] * rA, p01 = acc[j0][1] * rA;
      float p02 = acc[j0][2] * rB, p03 = acc[j0][3] * rB;
      float p10 = acc[j1][0] * rA, p11 = acc[j1][1] * rA;
      float p12 = acc[j1][2] * rB, p13 = acc[j1][3] * rB;
      ph[ky][0] = pack_hi(p00, p01); ph[ky][1] = pack_hi(p02, p03);
      ph[ky][2] = pack_hi(p10, p11); ph[ky][3] = pack_hi(p12, p13);
      pl[ky][0] = pack_lo(p00, p01); pl[ky][1] = pack_lo(p02, p03);
      pl[ky][2] = pack_lo(p10, p11); pl[ky][3] = pack_lo(p12, p13);
    }

    CP_WAIT1();          // V(q) done (QK(next) may pend)
    __syncthreads();     // visible to all warps

    // O = P V
    float oac[16][4];
#pragma unroll
    for (int j = 0; j < 16; j++)
#pragma unroll
      for (int e = 0; e < 4; e++) oac[j][e] = 0.f;

#pragma unroll
    for (int ky = 0; ky < 8; ky++) {
#pragma unroll
      for (int nt = 0; nt < 8; nt += 2) {
        uint32_t vh0[4], vl0[4], vh1[4], vl1[4];
        uint32_t bo0 = smb + AT_V + (uint32_t)((ky * 16 + lr) * 272 + nt * 32 + lc * 16);
        uint32_t bo1 = bo0 + 32;
        ldsm_x4_t(vh0, bo0);
        ldsm_x4_t(vl0, bo0 + 34816);
        ldsm_x4_t(vh1, bo1);
        ldsm_x4_t(vl1, bo1 + 34816);
        mma_bf16(oac[2 * nt],     ph[ky], vh0[0], vh0[1]);
        mma_bf16(oac[2 * nt + 1], ph[ky], vh0[2], vh0[3]);
        mma_bf16(oac[2 * nt + 2], ph[ky], vh1[0], vh1[1]);
        mma_bf16(oac[2 * nt + 3], ph[ky], vh1[2], vh1[3]);
        mma_bf16(oac[2 * nt],     ph[ky], vl0[0], vl0[1]);
        mma_bf16(oac[2 * nt + 1], ph[ky], vl0[2], vl0[3]);
        mma_bf16(oac[2 * nt + 2], ph[ky], vl1[0], vl1[1]);
        mma_bf16(oac[2 * nt + 3], ph[ky], vl1[2], vl1[3]);
        mma_bf16(oac[2 * nt],     pl[ky], vh0[0], vh0[1]);
        mma_bf16(oac[2 * nt + 1], pl[ky], vh0[2], vh0[3]);
        mma_bf16(oac[2 * nt + 2], pl[ky], vh1[0], vh1[1]);
        mma_bf16(oac[2 * nt + 3], pl[ky], vh1[2], vh1[3]);
      }
    }

    __syncthreads();     // all warps done reading V
    if (qn < nchan)      // prefetch V(next) — overlaps store + next S
      stage128(AT_V, qoff(qn) + (size_t)2 * NC * NHW);
    CP_COMMIT();

    // Epilogue: write O hi/lo bf16 at [q][row*128+col]
    const size_t ob = (size_t)q * NHW;
    const int row0 = r0 + g, row1 = r0 + g + 8;
#pragma unroll
    for (int j = 0; j < 16; j++) {
      int col = j * 8 + tig * 2;
      size_t o0 = ob + (size_t)row0 * 128 + col;
      size_t o1 = ob + (size_t)row1 * 128 + col;
      *(uint32_t*)(Oh + o0) = pack_hi(oac[j][0], oac[j][1]);
      *(uint32_t*)(Oh + o1) = pack_hi(oac[j][2], oac[j][3]);
      *(uint32_t*)(Ol + o0) = pack_lo(oac[j][0], oac[j][1]);
      *(uint32_t*)(Ol + o1) = pack_lo(oac[j][2], oac[j][3]);
    }
  }
}

// ---------------------------------------------------------------------------
extern "C" void kernel_launch(void* const* d_in, const int* in_sizes, int n_in,
                              void* d_out, int out_size) {
  const float* x  = (const float*)d_in[0];
  const float* wq = (const float*)d_in[1];
  const float* bq = (const float*)d_in[2];
  const float* wk = (const float*)d_in[3];
  const float* bk = (const float*)d_in[4];
  const float* wv = (const float*)d_in[5];
  const float* bv = (const float*)d_in[6];
  const float* wo = (const float*)d_in[7];
  const float* bo = (const float*)d_in[8];

  __nv_bfloat16 *xh, *xl, *qkvh, *qkvl, *ath, *atl, *wh, *wl;
  float* bias;
  cudaGetSymbolAddress((void**)&xh,   g_x_hi);
  cudaGetSymbolAddress((void**)&xl,   g_x_lo);
  cudaGetSymbolAddress((void**)&qkvh, g_qkv_hi);
  cudaGetSymbolAddress((void**)&qkvl, g_qkv_lo);
  cudaGetSymbolAddress((void**)&ath,  g_att_hi);
  cudaGetSymbolAddress((void**)&atl,  g_att_lo);
  cudaGetSymbolAddress((void**)&wh,   g_w_hi);
  cudaGetSymbolAddress((void**)&wl,   g_w_lo);
  cudaGetSymbolAddress((void**)&bias, g_bias);

  int nsm = 148;
  cudaDeviceGetAttribute(&nsm, cudaDevAttrMultiProcessorCount, 0);
  if (nsm > NB * NC) nsm = NB * NC;

  cudaFuncSetAttribute(gemm_mma,
                       cudaFuncAttributeMaxDynamicSharedMemorySize, SMEM_GEMM);
  cudaFuncSetAttribute(attn_mma,
                       cudaFuncAttributeMaxDynamicSharedMemorySize, SMEM_ATTN);

  // Convert inputs
  split_f32<<<NB * NC * NHW / 4 / 256, 256>>>(x, xh, xl);
  convert_w<<<dim3(NC * NC / 256, 4), 256>>>(wq, wk, wv, wo, bq, bk, bv, bo, wh, wl);

  // Fused QKV projection -> bf16 hi/lo
  gemm_mma<<<dim3(6, NHW / 128, NB), 256, SMEM_GEMM>>>(
      xh, xl, wh, wl, bias, nullptr, qkvh, qkvl, 3 * NC);

  // Persistent tensor-core attention -> bf16 hi/lo
  attn_mma<<<nsm, 256, SMEM_ATTN>>>(qkvh, qkvl, ath, atl);

  // Output projection -> fp32 d_out
  gemm_mma<<<dim3(2, NHW / 128, NB), 256, SMEM_GEMM>>>(
      ath, atl, wh + 3 * NC * NC, wl + 3 * NC * NC, bias + 3 * NC,
      (float*)d_out, nullptr, nullptr, NC);
}

// round 11
// speedup vs baseline: 1.0307x; 1.0074x over previous
#include <cuda_runtime.h>
#include <cuda_bf16.h>
#include <cstdint>
#include <math.h>

#define NB   8
#define NC   256
#define NH   128
#define NW   128
#define NHW  (NH * NW)        // 16384

// ---------------------------------------------------------------------------
// Scratch (device globals: allocation-guard safe)
// ---------------------------------------------------------------------------
__device__ __nv_bfloat16 g_x_hi[(size_t)NB * NC * NHW];      // [b][c][n]
__device__ __nv_bfloat16 g_x_lo[(size_t)NB * NC * NHW];
__device__ __nv_bfloat16 g_qkv_hi[(size_t)NB * 3 * NC * NHW]; // [b][3C][n]
__device__ __nv_bfloat16 g_qkv_lo[(size_t)NB * 3 * NC * NHW];
__device__ __nv_bfloat16 g_att_hi[(size_t)NB * NC * NHW];
__device__ __nv_bfloat16 g_att_lo[(size_t)NB * NC * NHW];
__device__ __nv_bfloat16 g_w_hi[4 * NC * NC];                // wq,wk,wv,wo [o][c]
__device__ __nv_bfloat16 g_w_lo[4 * NC * NC];
__device__ float g_bias[4 * NC];

// ---------------------------------------------------------------------------
// PTX helpers (sm_80-baseline tensor core path; valid on compute_103)
// ---------------------------------------------------------------------------
__device__ __forceinline__ uint32_t smem_u32(const void* p) {
  uint32_t a;
  asm("{ .reg .u64 t; cvta.to.shared.u64 t, %1; cvt.u32.u64 %0, t; }"
      : "=r"(a) : "l"(p));
  return a;
}
__device__ __forceinline__ void cp_async16(uint32_t sdst, const void* gsrc) {
  asm volatile("cp.async.cg.shared.global [%0], [%1], 16;"
               :: "r"(sdst), "l"(gsrc));
}
#define CP_COMMIT() asm volatile("cp.async.commit_group;" ::: "memory")
#define CP_WAIT0()  asm volatile("cp.async.wait_group 0;" ::: "memory")
#define CP_WAIT1()  asm volatile("cp.async.wait_group 1;" ::: "memory")

__device__ __forceinline__ void ldsm_x4(uint32_t* r, uint32_t addr) {
  asm volatile("ldmatrix.sync.aligned.m8n8.x4.shared.b16 {%0,%1,%2,%3}, [%4];"
               : "=r"(r[0]), "=r"(r[1]), "=r"(r[2]), "=r"(r[3]) : "r"(addr));
}
__device__ __forceinline__ void ldsm_x4_t(uint32_t* r, uint32_t addr) {
  asm volatile("ldmatrix.sync.aligned.m8n8.x4.trans.shared.b16 {%0,%1,%2,%3}, [%4];"
               : "=r"(r[0]), "=r"(r[1]), "=r"(r[2]), "=r"(r[3]) : "r"(addr));
}
__device__ __forceinline__ void mma_bf16(float* d, const uint32_t* a,
                                         uint32_t b0, uint32_t b1) {
  asm volatile(
      "mma.sync.aligned.m16n8k16.row.col.f32.bf16.bf16.f32 "
      "{%0,%1,%2,%3}, {%4,%5,%6,%7}, {%8,%9}, {%0,%1,%2,%3};"
      : "+f"(d[0]), "+f"(d[1]), "+f"(d[2]), "+f"(d[3])
      : "r"(a[0]), "r"(a[1]), "r"(a[2]), "r"(a[3]), "r"(b0), "r"(b1));
}
__device__ __forceinline__ float ex2(float x) {
  float r;
  asm("ex2.approx.f32 %0, %1;" : "=f"(r) : "f"(x));
  return r;
}
__device__ __forceinline__ uint32_t pack_hi(float a, float b) {
  __nv_bfloat162 p = {__float2bfloat16(a), __float2bfloat16(b)};
  return *(uint32_t*)&p;
}
__device__ __forceinline__ uint32_t pack_lo(float a, float b) {
  __nv_bfloat16 ha = __float2bfloat16(a), hb = __float2bfloat16(b);
  __nv_bfloat162 p = {__float2bfloat16(a - __bfloat162float(ha)),
                      __float2bfloat16(b - __bfloat162float(hb))};
  return *(uint32_t*)&p;
}

// ---------------------------------------------------------------------------
// Elementwise bf16 split: fp32 -> hi + lo (same layout)
// ---------------------------------------------------------------------------
__global__ __launch_bounds__(256) void split_f32(
    const float* __restrict__ X, __nv_bfloat16* __restrict__ H,
    __nv_bfloat16* __restrict__ L) {
  int i = blockIdx.x * 256 + threadIdx.x;
  float4 v = ((const float4*)X)[i];
  ((uint2*)H)[i] = make_uint2(pack_hi(v.x, v.y), pack_hi(v.z, v.w));
  ((uint2*)L)[i] = make_uint2(pack_lo(v.x, v.y), pack_lo(v.z, v.w));
}

__global__ __launch_bounds__(256) void convert_w(
    const float* __restrict__ w0, const float* __restrict__ w1,
    const float* __restrict__ w2, const float* __restrict__ w3,
    const float* __restrict__ b0, const float* __restrict__ b1,
    const float* __restrict__ b2, const float* __restrict__ b3,
    __nv_bfloat16* __restrict__ H, __nv_bfloat16* __restrict__ L) {
  const float* ws[4] = {w0, w1, w2, w3};
  const float* bs[4] = {b0, b1, b2, b3};
  int m = blockIdx.y;
  int i = blockIdx.x * 256 + threadIdx.x;
  float v = ws[m][i];
  __nv_bfloat16 h = __float2bfloat16(v);
  H[m * NC * NC + i] = h;
  L[m * NC * NC + i] = __float2bfloat16(v - __bfloat162float(h));
  if (blockIdx.x == 0) g_bias[m * NC + threadIdx.x] = bs[m][threadIdx.x];
}

// ---------------------------------------------------------------------------
// mma.sync bf16-split GEMM (R10 version — best measured, unchanged)
// ---------------------------------------------------------------------------
#define OFF_AH   0
#define OFF_AL   10240                 // 128*80
#define OFF_BH   20480
#define OFF_BL   29184                 // + 32*272
#define BUF_BYTES 37888
#define SMEM_GEMM (3 * BUF_BYTES)      // 113664

__global__ __launch_bounds__(256, 2) void gemm_mma(
    const __nv_bfloat16* __restrict__ Xh, const __nv_bfloat16* __restrict__ Xl,
    const __nv_bfloat16* __restrict__ Wh, const __nv_bfloat16* __restrict__ Wl,
    const float* __restrict__ bias, float* __restrict__ Yf,
    __nv_bfloat16* __restrict__ Yh, __nv_bfloat16* __restrict__ Yl,
    int ocnt) {
  extern __shared__ __align__(16) char sm[];
  const uint32_t smb = smem_u32(sm);

  const int tid  = threadIdx.x;
  const int lane = tid & 31;
  const int wid  = tid >> 5;
  const int wm   = wid & 3;
  const int wn   = wid >> 2;
  const int b    = blockIdx.z;
  const int o0   = blockIdx.x * 128;
  const int n0   = blockIdx.y * 128;

  const __nv_bfloat16* Xbh = Xh + (size_t)b * NC * NHW + n0;
  const __nv_bfloat16* Xbl = Xl + (size_t)b * NC * NHW + n0;
  const __nv_bfloat16* Wbh = Wh + (size_t)o0 * NC;
  const __nv_bfloat16* Wbl = Wl + (size_t)o0 * NC;

  const int a_row0 = tid >> 2, a_seg = tid & 3;
  const int b_row0 = tid >> 4, b_seg = tid & 15;

  float acc[2][8][4];
#pragma unroll
  for (int mt = 0; mt < 2; mt++)
#pragma unroll
    for (int nt = 0; nt < 8; nt++)
#pragma unroll
      for (int e = 0; e < 4; e++) acc[mt][nt][e] = 0.f;

  const int lr = lane & 15, lc = lane >> 4;
  uint32_t a_base = (uint32_t)((wm * 32 + lr) * 80 + lc * 16);
  uint32_t b_base = (uint32_t)(lr * 272 + wn * 128 + lc * 16);

  auto stage = [&](int it, int slot) {
    const int c0 = it * 32;
    const uint32_t sb = smb + slot * BUF_BYTES;
#pragma unroll
    for (int r = 0; r < 2; r++) {
      int row = a_row0 + r * 64;
      uint32_t so = (uint32_t)(row * 80 + a_seg * 16);
      cp_async16(sb + OFF_AH + so, Wbh + (size_t)row * NC + c0 + a_seg * 8);
      cp_async16(sb + OFF_AL + so, Wbl + (size_t)row * NC + c0 + a_seg * 8);
    }
#pragma unroll
    for (int r = 0; r < 2; r++) {
      int row = b_row0 + r * 16;
      uint32_t so = (uint32_t)(row * 272 + b_seg * 16);
      cp_async16(sb + OFF_BH + so, Xbh + (size_t)(c0 + row) * NHW + b_seg * 8);
      cp_async16(sb + OFF_BL + so, Xbl + (size_t)(c0 + row) * NHW + b_seg * 8);
    }
    CP_COMMIT();
  };

  stage(0, 0);
  stage(1, 1);

  int slot = 0;
  for (int it = 0; it < 8; it++) {
    if (it < 7) { CP_WAIT1(); } else { CP_WAIT0(); }
    __syncthreads();
    int pslot = slot + 2 >= 3 ? slot - 1 : slot + 2;
    if (it + 2 < 8) stage(it + 2, pslot);

    const uint32_t sb = smb + slot * BUF_BYTES;
#pragma unroll
    for (int ks = 0; ks < 2; ks++) {
      uint32_t ah[2][4], al[2][4];
#pragma unroll
      for (int mt = 0; mt < 2; mt++) {
        uint32_t ao = sb + a_base + (uint32_t)(mt * 16 * 80 + ks * 32);
        ldsm_x4(ah[mt], ao + OFF_AH);
        ldsm_x4(al[mt], ao + OFF_AL);
      }
#pragma unroll
      for (int nt2 = 0; nt2 < 4; nt2++) {
        uint32_t bh[4], bl[4];
        uint32_t bo = sb + b_base + (uint32_t)(ks * 16 * 272 + nt2 * 32);
        ldsm_x4_t(bh, bo + OFF_BH);
        ldsm_x4_t(bl, bo + OFF_BL);
        mma_bf16(acc[0][nt2 * 2],     ah[0], bh[0], bh[1]);   // hi*hi
        mma_bf16(acc[0][nt2 * 2 + 1], ah[0], bh[2], bh[3]);
        mma_bf16(acc[1][nt2 * 2],     ah[1], bh[0], bh[1]);
        mma_bf16(acc[1][nt2 * 2 + 1], ah[1], bh[2], bh[3]);
        mma_bf16(acc[0][nt2 * 2],     ah[0], bl[0], bl[1]);   // hi*lo
        mma_bf16(acc[0][nt2 * 2 + 1], ah[0], bl[2], bl[3]);
        mma_bf16(acc[1][nt2 * 2],     ah[1], bl[0], bl[1]);
        mma_bf16(acc[1][nt2 * 2 + 1], ah[1], bl[2], bl[3]);
        mma_bf16(acc[0][nt2 * 2],     al[0], bh[0], bh[1]);   // lo*hi
        mma_bf16(acc[0][nt2 * 2 + 1], al[0], bh[2], bh[3]);
        mma_bf16(acc[1][nt2 * 2],     al[1], bh[0], bh[1]);
        mma_bf16(acc[1][nt2 * 2 + 1], al[1], bh[2], bh[3]);
      }
    }
    slot = slot + 1 >= 3 ? 0 : slot + 1;
  }
  __syncthreads();

#pragma unroll
  for (int mt = 0; mt < 2; mt++) {
    int o = o0 + wm * 32 + mt * 16 + (lane >> 2);
    float bv0 = __ldg(bias + o);
    float bv1 = __ldg(bias + o + 8);
#pragma unroll
    for (int nt = 0; nt < 8; nt++) {
      int n = n0 + wn * 64 + nt * 8 + (lane & 3) * 2;
      float v00 = acc[mt][nt][0] + bv0, v01 = acc[mt][nt][1] + bv0;
      float v10 = acc[mt][nt][2] + bv1, v11 = acc[mt][nt][3] + bv1;
      size_t off0 = ((size_t)b * ocnt + o) * NHW + n;
      size_t off1 = ((size_t)b * ocnt + o + 8) * NHW + n;
      if (Yf) {
        *(float2*)(Yf + off0) = make_float2(v00, v01);
        *(float2*)(Yf + off1) = make_float2(v10, v11);
      } else {
        *(uint32_t*)(Yh + off0) = pack_hi(v00, v01);
        *(uint32_t*)(Yh + off1) = pack_hi(v10, v11);
        *(uint32_t*)(Yl + off0) = pack_lo(v00, v01);
        *(uint32_t*)(Yl + off1) = pack_lo(v10, v11);
      }
    }
  }
}

// ---------------------------------------------------------------------------
// Persistent tensor-core attention, shortened critical path:
//   wait1(QK)/sync -> S -> wait0(V)/sync -> QK(next) prefetch ->
//   exp-only softmax (no max, unnormalized P) -> PV (barrier-free entry) ->
//   sync -> V(next) prefetch -> epilogue (normalize by 1/rowsum here).
// 3 syncs/channel (was 4); exp = 1 FMUL + ex2.approx (scale folded in).
// ---------------------------------------------------------------------------
#define AT_Q 0
#define AT_K 69632
#define AT_V 139264
#define SMEM_ATTN 208896

__global__ __launch_bounds__(256) void attn_mma(
    const __nv_bfloat16* __restrict__ QKVh,
    const __nv_bfloat16* __restrict__ QKVl,
    __nv_bfloat16* __restrict__ Oh, __nv_bfloat16* __restrict__ Ol) {
  extern __shared__ __align__(16) char sm[];
  const uint32_t smb = smem_u32(sm);

  const int tid  = threadIdx.x;
  const int lane = tid & 31;
  const int wid  = tid >> 5;
  const int lr = lane & 15, lc = lane >> 4;
  const int g = lane >> 2, tig = lane & 3;
  const int r0 = wid * 16;
  const int srow = tid >> 4, sseg = tid & 15;
  const int nchan = NB * NC;

  auto stage128 = [&](uint32_t region, size_t goff) {
    const uint32_t sb = smb + region;
#pragma unroll
    for (int r = 0; r < 8; r++) {
      int row = srow + r * 16;
      uint32_t so = (uint32_t)(row * 272 + sseg * 16);
      cp_async16(sb + so,         QKVh + goff + row * 128 + sseg * 8);
      cp_async16(sb + 34816 + so, QKVl + goff + row * 128 + sseg * 8);
    }
  };
  auto qoff = [&](int q) {
    return ((size_t)(q >> 8) * 3 * NC + (q & 255)) * NHW;
  };

  // Prologue: QK(c0) [group], V(c0) [group]
  const int c0 = blockIdx.x;
  stage128(AT_Q, qoff(c0));
  stage128(AT_K, qoff(c0) + (size_t)NC * NHW);
  CP_COMMIT();
  stage128(AT_V, qoff(c0) + (size_t)2 * NC * NHW);
  CP_COMMIT();

  for (int q = c0; q < nchan; q += gridDim.x) {
    const int qn = q + gridDim.x;

    CP_WAIT1();          // QK(q) done (V(q) may pend)
    __syncthreads();     // QK visible to all warps

    // S = Q K^T
    float acc[16][4];
#pragma unroll
    for (int j = 0; j < 16; j++)
#pragma unroll
      for (int e = 0; e < 4; e++) acc[j][e] = 0.f;

#pragma unroll
    for (int ks = 0; ks < 8; ks++) {
      uint32_t qh[4], ql[4];
      uint32_t ao = smb + AT_Q + (uint32_t)((r0 + lr) * 272 + ks * 32 + lc * 16);
      ldsm_x4(qh, ao);
      ldsm_x4(ql, ao + 34816);
#pragma unroll
      for (int nt = 0; nt < 8; nt += 2) {
        uint32_t kh0[4], kl0[4], kh1[4], kl1[4];
        uint32_t bo0 = smb + AT_K + (uint32_t)((nt * 16 + lr) * 272 + ks * 32 + lc * 16);
        uint32_t bo1 = bo0 + 16 * 272;
        ldsm_x4(kh0, bo0);
        ldsm_x4(kl0, bo0 + 34816);
        ldsm_x4(kh1, bo1);
        ldsm_x4(kl1, bo1 + 34816);
        mma_bf16(acc[2 * nt],     qh, kh0[0], kh0[2]);
        mma_bf16(acc[2 * nt + 1], qh, kh0[1], kh0[3]);
        mma_bf16(acc[2 * nt + 2], qh, kh1[0], kh1[2]);
        mma_bf16(acc[2 * nt + 3], qh, kh1[1], kh1[3]);
        mma_bf16(acc[2 * nt],     qh, kl0[0], kl0[2]);
        mma_bf16(acc[2 * nt + 1], qh, kl0[1], kl0[3]);
        mma_bf16(acc[2 * nt + 2], qh, kl1[0], kl1[2]);
        mma_bf16(acc[2 * nt + 3], qh, kl1[1], kl1[3]);
        mma_bf16(acc[2 * nt],     ql, kh0[0], kh0[2]);
        mma_bf16(acc[2 * nt + 1], ql, kh0[1], kh0[3]);
        mma_bf16(acc[2 * nt + 2], ql, kh1[0], kh1[2]);
        mma_bf16(acc[2 * nt + 3], ql, kh1[1], kh1[3]);
      }
    }

    CP_WAIT0();          // V(q) done (only group in flight here)
    __syncthreads();     // V visible + all QK readers finished

    if (qn < nchan) {    // prefetch QK(next) — overlaps softmax+PV+epilogue
      stage128(AT_Q, qoff(qn));
      stage128(AT_K, qoff(qn) + (size_t)NC * NHW);
    }
    CP_COMMIT();

    // exp-only softmax: no max-subtract (|S·scale| <~ 40 — exp safe in fp32),
    // P left unnormalized; 1/rowsum applied in the O epilogue.
    // exp(S*scale) = ex2(S * (scale*log2e))
    const float C = 0.42044820762685725f * 1.4426950408889634f;
    float sA = 0.f, sB = 0.f;
#pragma unroll
    for (int j = 0; j < 16; j++) {
      acc[j][0] = ex2(acc[j][0] * C);
      acc[j][1] = ex2(acc[j][1] * C);
      acc[j][2] = ex2(acc[j][2] * C);
      acc[j][3] = ex2(acc[j][3] * C);
      sA += acc[j][0] + acc[j][1];
      sB += acc[j][2] + acc[j][3];
    }

    // Pack unnormalized P into A-operand fragments (hi/lo)
    uint32_t ph[8][4], pl[8][4];
#pragma unroll
    for (int ky = 0; ky < 8; ky++) {
      const int j0 = 2 * ky, j1 = 2 * ky + 1;
      ph[ky][0] = pack_hi(acc[j0][0], acc[j0][1]);
      ph[ky][1] = pack_hi(acc[j0][2], acc[j0][3]);
      ph[ky][2] = pack_hi(acc[j1][0], acc[j1][1]);
      ph[ky][3] = pack_hi(acc[j1][2], acc[j1][3]);
      pl[ky][0] = pack_lo(acc[j0][0], acc[j0][1]);
      pl[ky][1] = pack_lo(acc[j0][2], acc[j0][3]);
      pl[ky][2] = pack_lo(acc[j1][0], acc[j1][1]);
      pl[ky][3] = pack_lo(acc[j1][2], acc[j1][3]);
    }

    // Row-sum reduction (overlaps PV issue below)
    sA += __shfl_xor_sync(0xffffffffu, sA, 1);
    sA += __shfl_xor_sync(0xffffffffu, sA, 2);
    sB += __shfl_xor_sync(0xffffffffu, sB, 1);
    sB += __shfl_xor_sync(0xffffffffu, sB, 2);
    const float rA = 1.0f / sA, rB = 1.0f / sB;

    // O = P V (barrier-free entry)
    float oac[16][4];
#pragma unroll
    for (int j = 0; j < 16; j++)
#pragma unroll
      for (int e = 0; e < 4; e++) oac[j][e] = 0.f;

#pragma unroll
    for (int ky = 0; ky < 8; ky++) {
#pragma unroll
      for (int nt = 0; nt < 8; nt += 2) {
        uint32_t vh0[4], vl0[4], vh1[4], vl1[4];
        uint32_t bo0 = smb + AT_V + (uint32_t)((ky * 16 + lr) * 272 + nt * 32 + lc * 16);
        uint32_t bo1 = bo0 + 32;
        ldsm_x4_t(vh0, bo0);
        ldsm_x4_t(vl0, bo0 + 34816);
        ldsm_x4_t(vh1, bo1);
        ldsm_x4_t(vl1, bo1 + 34816);
        mma_bf16(oac[2 * nt],     ph[ky], vh0[0], vh0[1]);
        mma_bf16(oac[2 * nt + 1], ph[ky], vh0[2], vh0[3]);
        mma_bf16(oac[2 * nt + 2], ph[ky], vh1[0], vh1[1]);
        mma_bf16(oac[2 * nt + 3], ph[ky], vh1[2], vh1[3]);
        mma_bf16(oac[2 * nt],     ph[ky], vl0[0], vl0[1]);
        mma_bf16(oac[2 * nt + 1], ph[ky], vl0[2], vl0[3]);
        mma_bf16(oac[2 * nt + 2], ph[ky], vl1[0], vl1[1]);
        mma_bf16(oac[2 * nt + 3], ph[ky], vl1[2], vl1[3]);
        mma_bf16(oac[2 * nt],     pl[ky], vh0[0], vh0[1]);
        mma_bf16(oac[2 * nt + 1], pl[ky], vh0[2], vh0[3]);
        mma_bf16(oac[2 * nt + 2], pl[ky], vh1[0], vh1[1]);
        mma_bf16(oac[2 * nt + 3], pl[ky], vh1[2], vh1[3]);
      }
    }

    __syncthreads();     // all warps done reading V
    if (qn < nchan)      // prefetch V(next) — overlaps store + next S
      stage128(AT_V, qoff(qn) + (size_t)2 * NC * NHW);
    CP_COMMIT();

    // Epilogue: normalize rows here, write O hi/lo bf16 at [q][row*128+col]
    const size_t ob = (size_t)q * NHW;
    const int row0 = r0 + g, row1 = r0 + g + 8;
#pragma unroll
    for (int j = 0; j < 16; j++) {
      int col = j * 8 + tig * 2;
      float v00 = oac[j][0] * rA, v01 = oac[j][1] * rA;
      float v10 = oac[j][2] * rB, v11 = oac[j][3] * rB;
      size_t o0 = ob + (size_t)row0 * 128 + col;
      size_t o1 = ob + (size_t)row1 * 128 + col;
      *(uint32_t*)(Oh + o0) = pack_hi(v00, v01);
      *(uint32_t*)(Oh + o1) = pack_hi(v10, v11);
      *(uint32_t*)(Ol + o0) = pack_lo(v00, v01);
      *(uint32_t*)(Ol + o1) = pack_lo(v10, v11);
    }
  }
}

// ---------------------------------------------------------------------------
extern "C" void kernel_launch(void* const* d_in, const int* in_sizes, int n_in,
                              void* d_out, int out_size) {
  const float* x  = (const float*)d_in[0];
  const float* wq = (const float*)d_in[1];
  const float* bq = (const float*)d_in[2];
  const float* wk = (const float*)d_in[3];
  const float* bk = (const float*)d_in[4];
  const float* wv = (const float*)d_in[5];
  const float* bv = (const float*)d_in[6];
  const float* wo = (const float*)d_in[7];
  const float* bo = (const float*)d_in[8];

  __nv_bfloat16 *xh, *xl, *qkvh, *qkvl, *ath, *atl, *wh, *wl;
  float* bias;
  cudaGetSymbolAddress((void**)&xh,   g_x_hi);
  cudaGetSymbolAddress((void**)&xl,   g_x_lo);
  cudaGetSymbolAddress((void**)&qkvh, g_qkv_hi);
  cudaGetSymbolAddress((void**)&qkvl, g_qkv_lo);
  cudaGetSymbolAddress((void**)&ath,  g_att_hi);
  cudaGetSymbolAddress((void**)&atl,  g_att_lo);
  cudaGetSymbolAddress((void**)&wh,   g_w_hi);
  cudaGetSymbolAddress((void**)&wl,   g_w_lo);
  cudaGetSymbolAddress((void**)&bias, g_bias);

  int nsm = 148;
  cudaDeviceGetAttribute(&nsm, cudaDevAttrMultiProcessorCount, 0);
  if (nsm > NB * NC) nsm = NB * NC;

  cudaFuncSetAttribute(gemm_mma,
                       cudaFuncAttributeMaxDynamicSharedMemorySize, SMEM_GEMM);
  cudaFuncSetAttribute(attn_mma,
                       cudaFuncAttributeMaxDynamicSharedMemorySize, SMEM_ATTN);

  // Convert inputs
  split_f32<<<NB * NC * NHW / 4 / 256, 256>>>(x, xh, xl);
  convert_w<<<dim3(NC * NC / 256, 4), 256>>>(wq, wk, wv, wo, bq, bk, bv, bo, wh, wl);

  // Fused QKV projection -> bf16 hi/lo
  gemm_mma<<<dim3(6, NHW / 128, NB), 256, SMEM_GEMM>>>(
      xh, xl, wh, wl, bias, nullptr, qkvh, qkvl, 3 * NC);

  // Persistent tensor-core attention -> bf16 hi/lo
  attn_mma<<<nsm, 256, SMEM_ATTN>>>(qkvh, qkvl, ath, atl);

  // Output projection -> fp32 d_out
  gemm_mma<<<dim3(2, NHW / 128, NB), 256, SMEM_GEMM>>>(
      ath, atl, wh + 3 * NC * NC, wl + 3 * NC * NC, bias + 3 * NC,
      (float*)d_out, nullptr, nullptr, NC);
}

// round 12
// speedup vs baseline: 1.0333x; 1.0024x over previous
#include <cuda_runtime.h>
#include <cuda_bf16.h>
#include <cstdint>
#include <math.h>

#define NB   8
#define NC   256
#define NH   128
#define NW   128
#define NHW  (NH * NW)        // 16384

// ---------------------------------------------------------------------------
// Scratch (device globals: allocation-guard safe)
// ---------------------------------------------------------------------------
__device__ __nv_bfloat16 g_x_hi[(size_t)NB * NC * NHW];      // [b][c][n]
__device__ __nv_bfloat16 g_x_lo[(size_t)NB * NC * NHW];
__device__ __nv_bfloat16 g_qkv_hi[(size_t)NB * 3 * NC * NHW]; // [b][3C][n]
__device__ __nv_bfloat16 g_qkv_lo[(size_t)NB * 3 * NC * NHW];
__device__ __nv_bfloat16 g_att_hi[(size_t)NB * NC * NHW];
__device__ __nv_bfloat16 g_att_lo[(size_t)NB * NC * NHW];
__device__ __nv_bfloat16 g_w_hi[4 * NC * NC];                // wq,wk,wv,wo [o][c]
__device__ __nv_bfloat16 g_w_lo[4 * NC * NC];
__device__ float g_bias[4 * NC];

// ---------------------------------------------------------------------------
// PTX helpers (sm_80-baseline tensor core path; valid on compute_103)
// ---------------------------------------------------------------------------
__device__ __forceinline__ uint32_t smem_u32(const void* p) {
  uint32_t a;
  asm("{ .reg .u64 t; cvta.to.shared.u64 t, %1; cvt.u32.u64 %0, t; }"
      : "=r"(a) : "l"(p));
  return a;
}
__device__ __forceinline__ void cp_async16(uint32_t sdst, const void* gsrc) {
  asm volatile("cp.async.cg.shared.global [%0], [%1], 16;"
               :: "r"(sdst), "l"(gsrc));
}
#define CP_COMMIT() asm volatile("cp.async.commit_group;" ::: "memory")
#define CP_WAIT0()  asm volatile("cp.async.wait_group 0;" ::: "memory")
#define CP_WAIT1()  asm volatile("cp.async.wait_group 1;" ::: "memory")

__device__ __forceinline__ void ldsm_x4(uint32_t* r, uint32_t addr) {
  asm volatile("ldmatrix.sync.aligned.m8n8.x4.shared.b16 {%0,%1,%2,%3}, [%4];"
               : "=r"(r[0]), "=r"(r[1]), "=r"(r[2]), "=r"(r[3]) : "r"(addr));
}
__device__ __forceinline__ void ldsm_x4_t(uint32_t* r, uint32_t addr) {
  asm volatile("ldmatrix.sync.aligned.m8n8.x4.trans.shared.b16 {%0,%1,%2,%3}, [%4];"
               : "=r"(r[0]), "=r"(r[1]), "=r"(r[2]), "=r"(r[3]) : "r"(addr));
}
__device__ __forceinline__ void mma_bf16(float* d, const uint32_t* a,
                                         uint32_t b0, uint32_t b1) {
  asm volatile(
      "mma.sync.aligned.m16n8k16.row.col.f32.bf16.bf16.f32 "
      "{%0,%1,%2,%3}, {%4,%5,%6,%7}, {%8,%9}, {%0,%1,%2,%3};"
      : "+f"(d[0]), "+f"(d[1]), "+f"(d[2]), "+f"(d[3])
      : "r"(a[0]), "r"(a[1]), "r"(a[2]), "r"(a[3]), "r"(b0), "r"(b1));
}
__device__ __forceinline__ float ex2(float x) {
  float r;
  asm("ex2.approx.f32 %0, %1;" : "=f"(r) : "f"(x));
  return r;
}
__device__ __forceinline__ uint32_t pack_hi(float a, float b) {
  __nv_bfloat162 p = {__float2bfloat16(a), __float2bfloat16(b)};
  return *(uint32_t*)&p;
}
__device__ __forceinline__ uint32_t pack_lo(float a, float b) {
  __nv_bfloat16 ha = __float2bfloat16(a), hb = __float2bfloat16(b);
  __nv_bfloat162 p = {__float2bfloat16(a - __bfloat162float(ha)),
                      __float2bfloat16(b - __bfloat162float(hb))};
  return *(uint32_t*)&p;
}

// ---------------------------------------------------------------------------
// Elementwise bf16 split: fp32 -> hi + lo (same layout)
// ---------------------------------------------------------------------------
__global__ __launch_bounds__(256) void split_f32(
    const float* __restrict__ X, __nv_bfloat16* __restrict__ H,
    __nv_bfloat16* __restrict__ L) {
  int i = blockIdx.x * 256 + threadIdx.x;
  float4 v = ((const float4*)X)[i];
  ((uint2*)H)[i] = make_uint2(pack_hi(v.x, v.y), pack_hi(v.z, v.w));
  ((uint2*)L)[i] = make_uint2(pack_lo(v.x, v.y), pack_lo(v.z, v.w));
}

__global__ __launch_bounds__(256) void convert_w(
    const float* __restrict__ w0, const float* __restrict__ w1,
    const float* __restrict__ w2, const float* __restrict__ w3,
    const float* __restrict__ b0, const float* __restrict__ b1,
    const float* __restrict__ b2, const float* __restrict__ b3,
    __nv_bfloat16* __restrict__ H, __nv_bfloat16* __restrict__ L) {
  const float* ws[4] = {w0, w1, w2, w3};
  const float* bs[4] = {b0, b1, b2, b3};
  int m = blockIdx.y;
  int i = blockIdx.x * 256 + threadIdx.x;
  float v = ws[m][i];
  __nv_bfloat16 h = __float2bfloat16(v);
  H[m * NC * NC + i] = h;
  L[m * NC * NC + i] = __float2bfloat16(v - __bfloat162float(h));
  if (blockIdx.x == 0) g_bias[m * NC + threadIdx.x] = bs[m][threadIdx.x];
}

// ---------------------------------------------------------------------------
// mma.sync bf16-split GEMM (R10 version — best measured, unchanged)
// ---------------------------------------------------------------------------
#define OFF_AH   0
#define OFF_AL   10240                 // 128*80
#define OFF_BH   20480
#define OFF_BL   29184                 // + 32*272
#define BUF_BYTES 37888
#define SMEM_GEMM (3 * BUF_BYTES)      // 113664

__global__ __launch_bounds__(256, 2) void gemm_mma(
    const __nv_bfloat16* __restrict__ Xh, const __nv_bfloat16* __restrict__ Xl,
    const __nv_bfloat16* __restrict__ Wh, const __nv_bfloat16* __restrict__ Wl,
    const float* __restrict__ bias, float* __restrict__ Yf,
    __nv_bfloat16* __restrict__ Yh, __nv_bfloat16* __restrict__ Yl,
    int ocnt) {
  extern __shared__ __align__(16) char sm[];
  const uint32_t smb = smem_u32(sm);

  const int tid  = threadIdx.x;
  const int lane = tid & 31;
  const int wid  = tid >> 5;
  const int wm   = wid & 3;
  const int wn   = wid >> 2;
  const int b    = blockIdx.z;
  const int o0   = blockIdx.x * 128;
  const int n0   = blockIdx.y * 128;

  const __nv_bfloat16* Xbh = Xh + (size_t)b * NC * NHW + n0;
  const __nv_bfloat16* Xbl = Xl + (size_t)b * NC * NHW + n0;
  const __nv_bfloat16* Wbh = Wh + (size_t)o0 * NC;
  const __nv_bfloat16* Wbl = Wl + (size_t)o0 * NC;

  const int a_row0 = tid >> 2, a_seg = tid & 3;
  const int b_row0 = tid >> 4, b_seg = tid & 15;

  float acc[2][8][4];
#pragma unroll
  for (int mt = 0; mt < 2; mt++)
#pragma unroll
    for (int nt = 0; nt < 8; nt++)
#pragma unroll
      for (int e = 0; e < 4; e++) acc[mt][nt][e] = 0.f;

  const int lr = lane & 15, lc = lane >> 4;
  uint32_t a_base = (uint32_t)((wm * 32 + lr) * 80 + lc * 16);
  uint32_t b_base = (uint32_t)(lr * 272 + wn * 128 + lc * 16);

  auto stage = [&](int it, int slot) {
    const int c0 = it * 32;
    const uint32_t sb = smb + slot * BUF_BYTES;
#pragma unroll
    for (int r = 0; r < 2; r++) {
      int row = a_row0 + r * 64;
      uint32_t so = (uint32_t)(row * 80 + a_seg * 16);
      cp_async16(sb + OFF_AH + so, Wbh + (size_t)row * NC + c0 + a_seg * 8);
      cp_async16(sb + OFF_AL + so, Wbl + (size_t)row * NC + c0 + a_seg * 8);
    }
#pragma unroll
    for (int r = 0; r < 2; r++) {
      int row = b_row0 + r * 16;
      uint32_t so = (uint32_t)(row * 272 + b_seg * 16);
      cp_async16(sb + OFF_BH + so, Xbh + (size_t)(c0 + row) * NHW + b_seg * 8);
      cp_async16(sb + OFF_BL + so, Xbl + (size_t)(c0 + row) * NHW + b_seg * 8);
    }
    CP_COMMIT();
  };

  stage(0, 0);
  stage(1, 1);

  int slot = 0;
  for (int it = 0; it < 8; it++) {
    if (it < 7) { CP_WAIT1(); } else { CP_WAIT0(); }
    __syncthreads();
    int pslot = slot + 2 >= 3 ? slot - 1 : slot + 2;
    if (it + 2 < 8) stage(it + 2, pslot);

    const uint32_t sb = smb + slot * BUF_BYTES;
#pragma unroll
    for (int ks = 0; ks < 2; ks++) {
      uint32_t ah[2][4], al[2][4];
#pragma unroll
      for (int mt = 0; mt < 2; mt++) {
        uint32_t ao = sb + a_base + (uint32_t)(mt * 16 * 80 + ks * 32);
        ldsm_x4(ah[mt], ao + OFF_AH);
        ldsm_x4(al[mt], ao + OFF_AL);
      }
#pragma unroll
      for (int nt2 = 0; nt2 < 4; nt2++) {
        uint32_t bh[4], bl[4];
        uint32_t bo = sb + b_base + (uint32_t)(ks * 16 * 272 + nt2 * 32);
        ldsm_x4_t(bh, bo + OFF_BH);
        ldsm_x4_t(bl, bo + OFF_BL);
        mma_bf16(acc[0][nt2 * 2],     ah[0], bh[0], bh[1]);   // hi*hi
        mma_bf16(acc[0][nt2 * 2 + 1], ah[0], bh[2], bh[3]);
        mma_bf16(acc[1][nt2 * 2],     ah[1], bh[0], bh[1]);
        mma_bf16(acc[1][nt2 * 2 + 1], ah[1], bh[2], bh[3]);
        mma_bf16(acc[0][nt2 * 2],     ah[0], bl[0], bl[1]);   // hi*lo
        mma_bf16(acc[0][nt2 * 2 + 1], ah[0], bl[2], bl[3]);
        mma_bf16(acc[1][nt2 * 2],     ah[1], bl[0], bl[1]);
        mma_bf16(acc[1][nt2 * 2 + 1], ah[1], bl[2], bl[3]);
        mma_bf16(acc[0][nt2 * 2],     al[0], bh[0], bh[1]);   // lo*hi
        mma_bf16(acc[0][nt2 * 2 + 1], al[0], bh[2], bh[3]);
        mma_bf16(acc[1][nt2 * 2],     al[1], bh[0], bh[1]);
        mma_bf16(acc[1][nt2 * 2 + 1], al[1], bh[2], bh[3]);
      }
    }
    slot = slot + 1 >= 3 ? 0 : slot + 1;
  }
  __syncthreads();

#pragma unroll
  for (int mt = 0; mt < 2; mt++) {
    int o = o0 + wm * 32 + mt * 16 + (lane >> 2);
    float bv0 = __ldg(bias + o);
    float bv1 = __ldg(bias + o + 8);
#pragma unroll
    for (int nt = 0; nt < 8; nt++) {
      int n = n0 + wn * 64 + nt * 8 + (lane & 3) * 2;
      float v00 = acc[mt][nt][0] + bv0, v01 = acc[mt][nt][1] + bv0;
      float v10 = acc[mt][nt][2] + bv1, v11 = acc[mt][nt][3] + bv1;
      size_t off0 = ((size_t)b * ocnt + o) * NHW + n;
      size_t off1 = ((size_t)b * ocnt + o + 8) * NHW + n;
      if (Yf) {
        *(float2*)(Yf + off0) = make_float2(v00, v01);
        *(float2*)(Yf + off1) = make_float2(v10, v11);
      } else {
        *(uint32_t*)(Yh + off0) = pack_hi(v00, v01);
        *(uint32_t*)(Yh + off1) = pack_hi(v10, v11);
        *(uint32_t*)(Yl + off0) = pack_lo(v00, v01);
        *(uint32_t*)(Yl + off1) = pack_lo(v10, v11);
      }
    }
  }
}

// ---------------------------------------------------------------------------
// Persistent tensor-core attention, shortened critical path:
//   wait1(QK)/sync -> S -> wait0(V)/sync -> QK(next) prefetch ->
//   exp-only softmax (no max, unnormalized P) -> PV (barrier-free entry) ->
//   sync -> V(next) prefetch -> epilogue (normalize by 1/rowsum here).
// 3 syncs/channel (was 4); exp = 1 FMUL + ex2.approx (scale folded in).
// ---------------------------------------------------------------------------
#define AT_Q 0
#define AT_K 69632
#define AT_V 139264
#define SMEM_ATTN 208896

__global__ __launch_bounds__(256) void attn_mma(
    const __nv_bfloat16* __restrict__ QKVh,
    const __nv_bfloat16* __restrict__ QKVl,
    __nv_bfloat16* __restrict__ Oh, __nv_bfloat16* __restrict__ Ol) {
  extern __shared__ __align__(16) char sm[];
  const uint32_t smb = smem_u32(sm);

  const int tid  = threadIdx.x;
  const int lane = tid & 31;
  const int wid  = tid >> 5;
  const int lr = lane & 15, lc = lane >> 4;
  const int g = lane >> 2, tig = lane & 3;
  const int r0 = wid * 16;
  const int srow = tid >> 4, sseg = tid & 15;
  const int nchan = NB * NC;

  auto stage128 = [&](uint32_t region, size_t goff) {
    const uint32_t sb = smb + region;
#pragma unroll
    for (int r = 0; r < 8; r++) {
      int row = srow + r * 16;
      uint32_t so = (uint32_t)(row * 272 + sseg * 16);
      cp_async16(sb + so,         QKVh + goff + row * 128 + sseg * 8);
      cp_async16(sb + 34816 + so, QKVl + goff + row * 128 + sseg * 8);
    }
  };
  auto qoff = [&](int q) {
    return ((size_t)(q >> 8) * 3 * NC + (q & 255)) * NHW;
  };

  // Prologue: QK(c0) [group], V(c0) [group]
  const int c0 = blockIdx.x;
  stage128(AT_Q, qoff(c0));
  stage128(AT_K, qoff(c0) + (size_t)NC * NHW);
  CP_COMMIT();
  stage128(AT_V, qoff(c0) + (size_t)2 * NC * NHW);
  CP_COMMIT();

  for (int q = c0; q < nchan; q += gridDim.x) {
    const int qn = q + gridDim.x;

    CP_WAIT1();          // QK(q) done (V(q) may pend)
    __syncthreads();     // QK visible to all warps

    // S = Q K^T
    float acc[16][4];
#pragma unroll
    for (int j = 0; j < 16; j++)
#pragma unroll
      for (int e = 0; e < 4; e++) acc[j][e] = 0.f;

#pragma unroll
    for (int ks = 0; ks < 8; ks++) {
      uint32_t qh[4], ql[4];
      uint32_t ao = smb + AT_Q + (uint32_t)((r0 + lr) * 272 + ks * 32 + lc * 16);
      ldsm_x4(qh, ao);
      ldsm_x4(ql, ao + 34816);
#pragma unroll
      for (int nt = 0; nt < 8; nt += 2) {
        uint32_t kh0[4], kl0[4], kh1[4], kl1[4];
        uint32_t bo0 = smb + AT_K + (uint32_t)((nt * 16 + lr) * 272 + ks * 32 + lc * 16);
        uint32_t bo1 = bo0 + 16 * 272;
        ldsm_x4(kh0, bo0);
        ldsm_x4(kl0, bo0 + 34816);
        ldsm_x4(kh1, bo1);
        ldsm_x4(kl1, bo1 + 34816);
        mma_bf16(acc[2 * nt],     qh, kh0[0], kh0[2]);
        mma_bf16(acc[2 * nt + 1], qh, kh0[1], kh0[3]);
        mma_bf16(acc[2 * nt + 2], qh, kh1[0], kh1[2]);
        mma_bf16(acc[2 * nt + 3], qh, kh1[1], kh1[3]);
        mma_bf16(acc[2 * nt],     qh, kl0[0], kl0[2]);
        mma_bf16(acc[2 * nt + 1], qh, kl0[1], kl0[3]);
        mma_bf16(acc[2 * nt + 2], qh, kl1[0], kl1[2]);
        mma_bf16(acc[2 * nt + 3], qh, kl1[1], kl1[3]);
        mma_bf16(acc[2 * nt],     ql, kh0[0], kh0[2]);
        mma_bf16(acc[2 * nt + 1], ql, kh0[1], kh0[3]);
        mma_bf16(acc[2 * nt + 2], ql, kh1[0], kh1[2]);
        mma_bf16(acc[2 * nt + 3], ql, kh1[1], kh1[3]);
      }
    }

    CP_WAIT0();          // V(q) done (only group in flight here)
    __syncthreads();     // V visible + all QK readers finished

    if (qn < nchan) {    // prefetch QK(next) — overlaps softmax+PV+epilogue
      stage128(AT_Q, qoff(qn));
      stage128(AT_K, qoff(qn) + (size_t)NC * NHW);
    }
    CP_COMMIT();

    // exp-only softmax: no max-subtract (|S·scale| <~ 40 — exp safe in fp32),
    // P left unnormalized; 1/rowsum applied in the O epilogue.
    // exp(S*scale) = ex2(S * (scale*log2e))
    const float C = 0.42044820762685725f * 1.4426950408889634f;
    float sA = 0.f, sB = 0.f;
#pragma unroll
    for (int j = 0; j < 16; j++) {
      acc[j][0] = ex2(acc[j][0] * C);
      acc[j][1] = ex2(acc[j][1] * C);
      acc[j][2] = ex2(acc[j][2] * C);
      acc[j][3] = ex2(acc[j][3] * C);
      sA += acc[j][0] + acc[j][1];
      sB += acc[j][2] + acc[j][3];
    }

    // Pack unnormalized P into A-operand fragments (hi/lo)
    uint32_t ph[8][4], pl[8][4];
#pragma unroll
    for (int ky = 0; ky < 8; ky++) {
      const int j0 = 2 * ky, j1 = 2 * ky + 1;
      ph[ky][0] = pack_hi(acc[j0][0], acc[j0][1]);
      ph[ky][1] = pack_hi(acc[j0][2], acc[j0][3]);
      ph[ky][2] = pack_hi(acc[j1][0], acc[j1][1]);
      ph[ky][3] = pack_hi(acc[j1][2], acc[j1][3]);
      pl[ky][0] = pack_lo(acc[j0][0], acc[j0][1]);
      pl[ky][1] = pack_lo(acc[j0][2], acc[j0][3]);
      pl[ky][2] = pack_lo(acc[j1][0], acc[j1][1]);
      pl[ky][3] = pack_lo(acc[j1][2], acc[j1][3]);
    }

    // Row-sum reduction (overlaps PV issue below)
    sA += __shfl_xor_sync(0xffffffffu, sA, 1);
    sA += __shfl_xor_sync(0xffffffffu, sA, 2);
    sB += __shfl_xor_sync(0xffffffffu, sB, 1);
    sB += __shfl_xor_sync(0xffffffffu, sB, 2);
    const float rA = 1.0f / sA, rB = 1.0f / sB;

    // O = P V (barrier-free entry)
    float oac[16][4];
#pragma unroll
    for (int j = 0; j < 16; j++)
#pragma unroll
      for (int e = 0; e < 4; e++) oac[j][e] = 0.f;

#pragma unroll
    for (int ky = 0; ky < 8; ky++) {
#pragma unroll
      for (int nt = 0; nt < 8; nt += 2) {
        uint32_t vh0[4], vl0[4], vh1[4], vl1[4];
        uint32_t bo0 = smb + AT_V + (uint32_t)((ky * 16 + lr) * 272 + nt * 32 + lc * 16);
        uint32_t bo1 = bo0 + 32;
        ldsm_x4_t(vh0, bo0);
        ldsm_x4_t(vl0, bo0 + 34816);
        ldsm_x4_t(vh1, bo1);
        ldsm_x4_t(vl1, bo1 + 34816);
        mma_bf16(oac[2 * nt],     ph[ky], vh0[0], vh0[1]);
        mma_bf16(oac[2 * nt + 1], ph[ky], vh0[2], vh0[3]);
        mma_bf16(oac[2 * nt + 2], ph[ky], vh1[0], vh1[1]);
        mma_bf16(oac[2 * nt + 3], ph[ky], vh1[2], vh1[3]);
        mma_bf16(oac[2 * nt],     ph[ky], vl0[0], vl0[1]);
        mma_bf16(oac[2 * nt + 1], ph[ky], vl0[2], vl0[3]);
        mma_bf16(oac[2 * nt + 2], ph[ky], vl1[0], vl1[1]);
        mma_bf16(oac[2 * nt + 3], ph[ky], vl1[2], vl1[3]);
        mma_bf16(oac[2 * nt],     pl[ky], vh0[0], vh0[1]);
        mma_bf16(oac[2 * nt + 1], pl[ky], vh0[2], vh0[3]);
        mma_bf16(oac[2 * nt + 2], pl[ky], vh1[0], vh1[1]);
        mma_bf16(oac[2 * nt + 3], pl[ky], vh1[2], vh1[3]);
      }
    }

    __syncthreads();     // all warps done reading V
    if (qn < nchan)      // prefetch V(next) — overlaps store + next S
      stage128(AT_V, qoff(qn) + (size_t)2 * NC * NHW);
    CP_COMMIT();

    // Epilogue: normalize rows here, write O hi/lo bf16 at [q][row*128+col]
    const size_t ob = (size_t)q * NHW;
    const int row0 = r0 + g, row1 = r0 + g + 8;
#pragma unroll
    for (int j = 0; j < 16; j++) {
      int col = j * 8 + tig * 2;
      float v00 = oac[j][0] * rA, v01 = oac[j][1] * rA;
      float v10 = oac[j][2] * rB, v11 = oac[j][3] * rB;
      size_t o0 = ob + (size_t)row0 * 128 + col;
      size_t o1 = ob + (size_t)row1 * 128 + col;
      *(uint32_t*)(Oh + o0) = pack_hi(v00, v01);
      *(uint32_t*)(Oh + o1) = pack_hi(v10, v11);
      *(uint32_t*)(Ol + o0) = pack_lo(v00, v01);
      *(uint32_t*)(Ol + o1) = pack_lo(v10, v11);
    }
  }
}

// ---------------------------------------------------------------------------
extern "C" void kernel_launch(void* const* d_in, const int* in_sizes, int n_in,
                              void* d_out, int out_size) {
  const float* x  = (const float*)d_in[0];
  const float* wq = (const float*)d_in[1];
  const float* bq = (const float*)d_in[2];
  const float* wk = (const float*)d_in[3];
  const float* bk = (const float*)d_in[4];
  const float* wv = (const float*)d_in[5];
  const float* bv = (const float*)d_in[6];
  const float* wo = (const float*)d_in[7];
  const float* bo = (const float*)d_in[8];

  __nv_bfloat16 *xh, *xl, *qkvh, *qkvl, *ath, *atl, *wh, *wl;
  float* bias;
  cudaGetSymbolAddress((void**)&xh,   g_x_hi);
  cudaGetSymbolAddress((void**)&xl,   g_x_lo);
  cudaGetSymbolAddress((void**)&qkvh, g_qkv_hi);
  cudaGetSymbolAddress((void**)&qkvl, g_qkv_lo);
  cudaGetSymbolAddress((void**)&ath,  g_att_hi);
  cudaGetSymbolAddress((void**)&atl,  g_att_lo);
  cudaGetSymbolAddress((void**)&wh,   g_w_hi);
  cudaGetSymbolAddress((void**)&wl,   g_w_lo);
  cudaGetSymbolAddress((void**)&bias, g_bias);

  int nsm = 148;
  cudaDeviceGetAttribute(&nsm, cudaDevAttrMultiProcessorCount, 0);
  if (nsm > NB * NC) nsm = NB * NC;

  cudaFuncSetAttribute(gemm_mma,
                       cudaFuncAttributeMaxDynamicSharedMemorySize, SMEM_GEMM);
  cudaFuncSetAttribute(attn_mma,
                       cudaFuncAttributeMaxDynamicSharedMemorySize, SMEM_ATTN);

  // Convert inputs
  split_f32<<<NB * NC * NHW / 4 / 256, 256>>>(x, xh, xl);
  convert_w<<<dim3(NC * NC / 256, 4), 256>>>(wq, wk, wv, wo, bq, bk, bv, bo, wh, wl);

  // Fused QKV projection -> bf16 hi/lo
  gemm_mma<<<dim3(6, NHW / 128, NB), 256, SMEM_GEMM>>>(
      xh, xl, wh, wl, bias, nullptr, qkvh, qkvl, 3 * NC);

  // Persistent tensor-core attention -> bf16 hi/lo
  attn_mma<<<nsm, 256, SMEM_ATTN>>>(qkvh, qkvl, ath, atl);

  // Output projection -> fp32 d_out
  gemm_mma<<<dim3(2, NHW / 128, NB), 256, SMEM_GEMM>>>(
      ath, atl, wh + 3 * NC * NC, wl + 3 * NC * NC, bias + 3 * NC,
      (float*)d_out, nullptr, nullptr, NC);
}